// round 2
// baseline (speedup 1.0000x reference)
#include <cuda_runtime.h>

#define E_EDGES 2000000
#define N_NODES 50000
#define D 32

// ---------------- scratch (static device globals; no runtime alloc) ----------------
__device__ float g_s0[N_NODES * D];            // segment sums, layer 0
__device__ float g_s1[N_NODES * D];            // segment sums, layer 1
__device__ float g_h1[(size_t)E_EDGES * D];    // h after layer 0, row-major [E][D]
__device__ float g_vals[E_EDGES];              // head logits
__device__ int   g_mi[N_NODES];                // per-node max (order-encoded int)
__device__ float g_dsum[N_NODES];              // softmax denominators

__device__ __forceinline__ float lrelu(float x) { return fmaxf(x, 0.01f * x); }

// order-preserving float<->int encoding for atomicMax
__device__ __forceinline__ int fenc(float f) {
    int i = __float_as_int(f);
    return i >= 0 ? i : (i ^ 0x7FFFFFFF);
}
__device__ __forceinline__ float fdec(int i) {
    return __int_as_float(i >= 0 ? i : (i ^ 0x7FFFFFFF));
}

// vectorized fire-and-forget reductions (sm_90+)
__device__ __forceinline__ void red_add4(float* p, float4 v) {
    asm volatile("red.global.add.v4.f32 [%0], {%1,%2,%3,%4};"
                 :: "l"(p), "f"(v.x), "f"(v.y), "f"(v.z), "f"(v.w) : "memory");
}
__device__ __forceinline__ void red_add1(float* p, float v) {
    asm volatile("red.global.add.f32 [%0], %1;" :: "l"(p), "f"(v) : "memory");
}

// ---- dual-edge 32x32 matmul helpers: one weight LDS feeds both edges ------------
// y{0,1} += x{0,1} @ W   (y pre-initialized with bias / partial sums)
__device__ __forceinline__ void mm_acc2(const float* __restrict__ x0,
                                        const float* __restrict__ x1,
                                        const float* __restrict__ sW,
                                        float* __restrict__ y0,
                                        float* __restrict__ y1) {
#pragma unroll
    for (int d = 0; d < D; d += 4) {
        float4 A = make_float4(y0[d], y0[d + 1], y0[d + 2], y0[d + 3]);
        float4 B = make_float4(y1[d], y1[d + 1], y1[d + 2], y1[d + 3]);
#pragma unroll
        for (int k = 0; k < D; ++k) {
            float4 w = *(const float4*)&sW[k * D + d];
            float a = x0[k], b = x1[k];
            A.x = fmaf(a, w.x, A.x);  B.x = fmaf(b, w.x, B.x);
            A.y = fmaf(a, w.y, A.y);  B.y = fmaf(b, w.y, B.y);
            A.z = fmaf(a, w.z, A.z);  B.z = fmaf(b, w.z, B.z);
            A.w = fmaf(a, w.w, A.w);  B.w = fmaf(b, w.w, B.w);
        }
        y0[d] = A.x; y0[d + 1] = A.y; y0[d + 2] = A.z; y0[d + 3] = A.w;
        y1[d] = B.x; y1[d + 1] = B.y; y1[d + 2] = B.z; y1[d + 3] = B.w;
    }
}

// red_add( (x{0,1} @ W + b) ) into p0 / p1 (p1 predicated)
__device__ __forceinline__ void mm_red2(const float* __restrict__ x0,
                                        const float* __restrict__ x1,
                                        const float* __restrict__ sW,
                                        const float* __restrict__ sB,
                                        float* p0, float* p1, bool v1) {
#pragma unroll
    for (int d = 0; d < D; d += 4) {
        float4 A = *(const float4*)&sB[d];
        float4 B = A;
#pragma unroll
        for (int k = 0; k < D; ++k) {
            float4 w = *(const float4*)&sW[k * D + d];
            float a = x0[k], b = x1[k];
            A.x = fmaf(a, w.x, A.x);  B.x = fmaf(b, w.x, B.x);
            A.y = fmaf(a, w.y, A.y);  B.y = fmaf(b, w.y, B.y);
            A.z = fmaf(a, w.z, A.z);  B.z = fmaf(b, w.z, B.z);
            A.w = fmaf(a, w.w, A.w);  B.w = fmaf(b, w.w, B.w);
        }
        red_add4(p0 + d, A);
        if (v1) red_add4(p1 + d, B);
    }
}

__device__ __forceinline__ void lrelu32(float* y) {
#pragma unroll
    for (int d = 0; d < D; ++d) y[d] = lrelu(y[d]);
}

__device__ __forceinline__ void ld32v4(const float* p, float* y) {
#pragma unroll
    for (int j = 0; j < D / 4; ++j) {
        float4 v = ((const float4*)p)[j];
        y[4 * j] = v.x; y[4 * j + 1] = v.y; y[4 * j + 2] = v.z; y[4 * j + 3] = v.w;
    }
}

// ---------------- init: zero accumulators ----------------
__global__ void kinit() {
    int i = blockIdx.x * blockDim.x + threadIdx.x;
    if (i < N_NODES * D) { g_s0[i] = 0.f; g_s1[i] = 0.f; }
    if (i < N_NODES)     { g_mi[i] = (int)0x80000000; g_dsum[i] = 0.f; }
}

// ---------------- K0: t0 = TMLP0(h0(a)) folded; scatter into s0 ----------------
__global__ __launch_bounds__(128)
void k0(const float* __restrict__ ea, const int* __restrict__ idx,
        const float* __restrict__ w_in, const float* __restrict__ b_in,
        const float* __restrict__ tw1, const float* __restrict__ tb1,
        const float* __restrict__ tw2, const float* __restrict__ tb2) {
    __shared__ float sP[D], sQ[D], sW2[D * D], sB2[D];
    int t = threadIdx.x;
    if (t < D) {
        float p = 0.f, q = 0.f;
        for (int k = 0; k < D; ++k) {
            p = fmaf(w_in[k], tw1[k * D + t], p);
            q = fmaf(b_in[k], tw1[k * D + t], q);
        }
        sP[t] = p; sQ[t] = q + tb1[t]; sB2[t] = tb2[t];
    }
    for (int i = t; i < D * D; i += 128) sW2[i] = tw2[i];
    __syncthreads();

    int base = blockIdx.x * 256;
    int e0 = base + t, e1 = e0 + 128;
    if (e0 >= E_EDGES) return;
    bool v1 = e1 < E_EDGES;

    float a0 = ea[e0];
    float a1 = v1 ? ea[e1] : 0.f;
    int n0 = idx[e0];
    int n1 = v1 ? idx[e1] : 0;

    float z0[D], z1[D];
#pragma unroll
    for (int d = 0; d < D; ++d) {
        z0[d] = lrelu(fmaf(a0, sP[d], sQ[d]));
        z1[d] = lrelu(fmaf(a1, sP[d], sQ[d]));
    }
    mm_red2(z0, z1, sW2, sB2, g_s0 + (size_t)n0 * D, g_s0 + (size_t)n1 * D, v1);
}

// ---------------- K1: h1 = UPD0(h0, s0[idx]); t1 = TMLP1(h1); scatter s1; store h1 ----
__global__ __launch_bounds__(128)
void k1(const float* __restrict__ ea, const int* __restrict__ idx,
        const float* __restrict__ w_in, const float* __restrict__ b_in,
        const float* __restrict__ tw1, const float* __restrict__ tb1,
        const float* __restrict__ tw2, const float* __restrict__ tb2,
        const float* __restrict__ uw1, const float* __restrict__ ub1,
        const float* __restrict__ uw2, const float* __restrict__ ub2) {
    __shared__ float sP[D], sQ[D];                 // h0 folded through uw1[0][0:32]
    __shared__ float sU1b[D * D];                  // uw1[0][32:64]
    __shared__ float sU2[D * D], sUB2[D];          // uw2[0], ub2[0]
    __shared__ float sT1[D * D], sTB1[D];          // tw1[1], tb1[1]
    __shared__ float sT2[D * D], sTB2[D];          // tw2[1], tb2[1]
    int t = threadIdx.x;
    if (t < D) {
        float p = 0.f, q = 0.f;
        for (int k = 0; k < D; ++k) {
            p = fmaf(w_in[k], uw1[k * D + t], p);
            q = fmaf(b_in[k], uw1[k * D + t], q);
        }
        sP[t] = p; sQ[t] = q + ub1[t];
        sUB2[t] = ub2[t]; sTB1[t] = tb1[D + t]; sTB2[t] = tb2[D + t];
    }
    for (int i = t; i < D * D; i += 128) {
        sU1b[i] = uw1[D * D + i];      // rows 32..63 of uw1[0]
        sU2[i]  = uw2[i];
        sT1[i]  = tw1[D * D + i];      // tw1[1]
        sT2[i]  = tw2[D * D + i];      // tw2[1]
    }
    __syncthreads();

    int base = blockIdx.x * 256;
    int e0 = base + t, e1 = e0 + 128;
    if (e0 >= E_EDGES) return;
    bool v1 = e1 < E_EDGES;

    float a0 = ea[e0];
    float a1 = v1 ? ea[e1] : 0.f;
    int n0 = idx[e0];
    int n1 = v1 ? idx[e1] : 0;

    float z0[D], z1[D];
    {
        float sg0[D], sg1[D];
        ld32v4(g_s0 + (size_t)n0 * D, sg0);
        ld32v4(g_s0 + (size_t)n1 * D, sg1);
#pragma unroll
        for (int d = 0; d < D; ++d) {
            z0[d] = fmaf(a0, sP[d], sQ[d]);
            z1[d] = fmaf(a1, sP[d], sQ[d]);
        }
        mm_acc2(sg0, sg1, sU1b, z0, z1);
        lrelu32(z0); lrelu32(z1);
    }

    float h0a[D], h1a[D];
#pragma unroll
    for (int d = 0; d < D; ++d) { h0a[d] = sUB2[d]; h1a[d] = sUB2[d]; }
    mm_acc2(z0, z1, sU2, h0a, h1a);

    // persist h1 row-major [E][D] (float4)
    {
        float4* p0 = (float4*)(g_h1 + (size_t)e0 * D);
#pragma unroll
        for (int j = 0; j < D / 4; ++j)
            p0[j] = make_float4(h0a[4 * j], h0a[4 * j + 1], h0a[4 * j + 2], h0a[4 * j + 3]);
        if (v1) {
            float4* p1 = (float4*)(g_h1 + (size_t)e1 * D);
#pragma unroll
            for (int j = 0; j < D / 4; ++j)
                p1[j] = make_float4(h1a[4 * j], h1a[4 * j + 1], h1a[4 * j + 2], h1a[4 * j + 3]);
        }
    }

    // t1 = lrelu(h1@T1 + TB1) @ T2 + TB2; scatter into s1
#pragma unroll
    for (int d = 0; d < D; ++d) { z0[d] = sTB1[d]; z1[d] = sTB1[d]; }
    mm_acc2(h0a, h1a, sT1, z0, z1);
    lrelu32(z0); lrelu32(z1);

    mm_red2(z0, z1, sT2, sTB2, g_s1 + (size_t)n0 * D, g_s1 + (size_t)n1 * D, v1);
}

// ---------------- K2: h2 = UPD1(h1, s1[idx]); head -> logits; atomicMax per node ----
__global__ __launch_bounds__(128)
void k2(const float* __restrict__ ea, const int* __restrict__ idx,
        const float* __restrict__ w_in, const float* __restrict__ b_in,
        const float* __restrict__ uw1, const float* __restrict__ ub1,
        const float* __restrict__ uw2, const float* __restrict__ ub2,
        const float* __restrict__ hw1, const float* __restrict__ hb1,
        const float* __restrict__ hw2, const float* __restrict__ hb2,
        const float* __restrict__ hw3, const float* __restrict__ hb3) {
    __shared__ float sU1a[D * D], sU1b[D * D], sU2[D * D], sUB1[D], sUB2[D];
    __shared__ float sPH[D], sQH[D];               // h0 folded through hw1[0:32]
    __shared__ float sH1b[D * D], sH2[D * D], sHB2[D], sH3[D];
    __shared__ float sHB3;
    int t = threadIdx.x;
    const float* u1 = uw1 + 2 * D * D;             // uw1[1]
    if (t < D) {
        float p = 0.f, q = 0.f;
        for (int k = 0; k < D; ++k) {
            p = fmaf(w_in[k], hw1[k * D + t], p);
            q = fmaf(b_in[k], hw1[k * D + t], q);
        }
        sPH[t] = p; sQH[t] = q + hb1[t];
        sUB1[t] = ub1[D + t]; sUB2[t] = ub2[D + t]; sHB2[t] = hb2[t]; sH3[t] = hw3[t];
    }
    if (t == 0) sHB3 = hb3[0];
    for (int i = t; i < D * D; i += 128) {
        sU1a[i] = u1[i];
        sU1b[i] = u1[D * D + i];
        sU2[i]  = uw2[D * D + i];
        sH1b[i] = hw1[D * D + i];
        sH2[i]  = hw2[i];
    }
    __syncthreads();

    int base = blockIdx.x * 256;
    int e0 = base + t, e1 = e0 + 128;
    if (e0 >= E_EDGES) return;
    bool v1 = e1 < E_EDGES;

    float a0 = ea[e0];
    float a1 = v1 ? ea[e1] : 0.f;
    int n0 = idx[e0];
    int n1 = v1 ? idx[e1] : 0;

    // pass 1: z = UB1 + h1 @ U1a   (h1 live only here)
    float z0[D], z1[D];
    {
        float h10[D], h11[D];
        ld32v4(g_h1 + (size_t)e0 * D, h10);
        if (v1) ld32v4(g_h1 + (size_t)e1 * D, h11);
        else {
#pragma unroll
            for (int d = 0; d < D; ++d) h11[d] = 0.f;
        }
#pragma unroll
        for (int d = 0; d < D; ++d) { z0[d] = sUB1[d]; z1[d] = sUB1[d]; }
        mm_acc2(h10, h11, sU1a, z0, z1);
    }
    // pass 2: z += sg @ U1b ; lrelu
    {
        float sg0[D], sg1[D];
        ld32v4(g_s1 + (size_t)n0 * D, sg0);
        ld32v4(g_s1 + (size_t)n1 * D, sg1);
        mm_acc2(sg0, sg1, sU1b, z0, z1);
        lrelu32(z0); lrelu32(z1);
    }

    // h2 = z @ U2 + UB2
    float h20[D], h21[D];
#pragma unroll
    for (int d = 0; d < D; ++d) { h20[d] = sUB2[d]; h21[d] = sUB2[d]; }
    mm_acc2(z0, z1, sU2, h20, h21);

    // v1 = lrelu(a*PH + QH + h2 @ H1b)   (reuse z arrays)
#pragma unroll
    for (int d = 0; d < D; ++d) {
        z0[d] = fmaf(a0, sPH[d], sQH[d]);
        z1[d] = fmaf(a1, sPH[d], sQH[d]);
    }
    mm_acc2(h20, h21, sH1b, z0, z1);
    lrelu32(z0); lrelu32(z1);

    // v2 = lrelu(v1 @ H2 + HB2)    (reuse h2 arrays)
#pragma unroll
    for (int d = 0; d < D; ++d) { h20[d] = sHB2[d]; h21[d] = sHB2[d]; }
    mm_acc2(z0, z1, sH2, h20, h21);
    lrelu32(h20); lrelu32(h21);

    float val0 = sHB3, val1 = sHB3;
#pragma unroll
    for (int k = 0; k < D; ++k) {
        val0 = fmaf(h20[k], sH3[k], val0);
        val1 = fmaf(h21[k], sH3[k], val1);
    }

    g_vals[e0] = val0;
    atomicMax(&g_mi[n0], fenc(val0));
    if (v1) {
        g_vals[e1] = val1;
        atomicMax(&g_mi[n1], fenc(val1));
    }
}

// ---------------- K3: e = exp(v - m[idx]); accumulate denom; stage e in out --------
__global__ void k3(const int* __restrict__ idx, float* __restrict__ out) {
    int e = blockIdx.x * blockDim.x + threadIdx.x;
    if (e >= E_EDGES) return;
    int node = idx[e];
    float m = fdec(g_mi[node]);
    float ex = expf(g_vals[e] - m);
    red_add1(&g_dsum[node], ex);
    out[e] = ex;
}

// ---------------- K4: normalize --------------------------------------------------
__global__ void k4(const int* __restrict__ idx, float* __restrict__ out) {
    int e = blockIdx.x * blockDim.x + threadIdx.x;
    if (e >= E_EDGES) return;
    out[e] = out[e] / g_dsum[idx[e]];
}

// ---------------- launcher --------------------------------------------------------
extern "C" void kernel_launch(void* const* d_in, const int* in_sizes, int n_in,
                              void* d_out, int out_size) {
    const float* ea   = (const float*)d_in[0];
    const int*   eidx = (const int*)d_in[1];   // row 0 = source nodes
    const float* w_in = (const float*)d_in[2];
    const float* b_in = (const float*)d_in[3];
    const float* tw1  = (const float*)d_in[4];
    const float* tb1  = (const float*)d_in[5];
    const float* tw2  = (const float*)d_in[6];
    const float* tb2  = (const float*)d_in[7];
    const float* uw1  = (const float*)d_in[8];
    const float* ub1  = (const float*)d_in[9];
    const float* uw2  = (const float*)d_in[10];
    const float* ub2  = (const float*)d_in[11];
    const float* hw1  = (const float*)d_in[12];
    const float* hb1  = (const float*)d_in[13];
    const float* hw2  = (const float*)d_in[14];
    const float* hb2  = (const float*)d_in[15];
    const float* hw3  = (const float*)d_in[16];
    const float* hb3  = (const float*)d_in[17];
    float* out = (float*)d_out;

    const int TB = 256;
    kinit<<<(N_NODES * D + TB - 1) / TB, TB>>>();
    int gbd = (E_EDGES + 255) / 256;   // dual-edge kernels: 128 threads, 256 edges/block
    k0<<<gbd, 128>>>(ea, eidx, w_in, b_in, tw1, tb1, tw2, tb2);
    k1<<<gbd, 128>>>(ea, eidx, w_in, b_in, tw1, tb1, tw2, tb2, uw1, ub1, uw2, ub2);
    k2<<<gbd, 128>>>(ea, eidx, w_in, b_in, uw1, ub1, uw2, ub2,
                     hw1, hb1, hw2, hb2, hw3, hb3);
    int gb = (E_EDGES + TB - 1) / TB;
    k3<<<gb, TB>>>(eidx, out);
    k4<<<gb, TB>>>(eidx, out);
}

// round 3
// speedup vs baseline: 3.2997x; 3.2997x over previous
#include <cuda_runtime.h>

#define E_EDGES 2000000
#define N_NODES 50000
#define D 32
#define NTILES (E_EDGES / 16)

// ---------------- scratch ----------------
__device__ float g_s0[N_NODES * D];            // segment sums layer 0 (tau-space)
__device__ float g_s1[N_NODES * D];            // segment sums layer 1 (tau-space)
__device__ float g_h1[(size_t)E_EDGES * D];    // h after layer 0 (tau-space, [E][32])
__device__ float g_vals[E_EDGES];              // head logits
__device__ int   g_mi[N_NODES];                // per-node max (order-encoded)
__device__ float g_dsum[N_NODES];              // softmax denominators

__device__ __forceinline__ float lrelu(float x) { return fmaxf(x, 0.01f * x); }
__device__ __forceinline__ int fenc(float f) {
    int i = __float_as_int(f);
    return i >= 0 ? i : (i ^ 0x7FFFFFFF);
}
__device__ __forceinline__ float fdec(int i) {
    return __int_as_float(i >= 0 ? i : (i ^ 0x7FFFFFFF));
}
__device__ __forceinline__ void red_add2(float* p, float a, float b) {
    asm volatile("red.global.add.v2.f32 [%0], {%1,%2};" :: "l"(p), "f"(a), "f"(b) : "memory");
}
__device__ __forceinline__ void red_add1(float* p, float v) {
    asm volatile("red.global.add.f32 [%0], %1;" :: "l"(p), "f"(v) : "memory");
}

// tau permutation within each 8-block: tau(2q)=q, tau(2q+1)=q+4
__device__ __forceinline__ int tau_(int u) {
    int b = u & ~7, v = u & 7;
    return b + ((v & 1) ? (v >> 1) + 4 : (v >> 1));
}

__device__ __forceinline__ unsigned cvt_tf32(float f) {
    unsigned r; asm("cvt.rna.tf32.f32 %0, %1;" : "=r"(r) : "f"(f)); return r;
}

__device__ __forceinline__ void mma8(float& c0, float& c1, float& c2, float& c3,
                                     unsigned a0, unsigned a1, unsigned a2, unsigned a3,
                                     unsigned b0, unsigned b1) {
    asm("mma.sync.aligned.m16n8k8.row.col.f32.tf32.tf32.f32 "
        "{%0,%1,%2,%3},{%4,%5,%6,%7},{%8,%9},{%0,%1,%2,%3};"
        : "+f"(c0), "+f"(c1), "+f"(c2), "+f"(c3)
        : "r"(a0), "r"(a1), "r"(a2), "r"(a3), "r"(b0), "r"(b1));
}

// C[16,32] += A[16,32] @ W   (4 kblocks x 4 nblocks)
__device__ __forceinline__ void mm_tile(const unsigned A[4][4], const uint2* sB,
                                        float C[4][4], int lane) {
#pragma unroll
    for (int kb = 0; kb < 4; kb++)
#pragma unroll
        for (int nb = 0; nb < 4; nb++) {
            uint2 b = sB[(kb * 4 + nb) * 32 + lane];
            mma8(C[nb][0], C[nb][1], C[nb][2], C[nb][3],
                 A[kb][0], A[kb][1], A[kb][2], A[kb][3], b.x, b.y);
        }
}

// chain: C-frag (tau-space) -> A-frag of next matmul. (a0,a1,a2,a3)=(c0,c2,c1,c3)
__device__ __forceinline__ void c2a(const float C[4][4], unsigned A[4][4]) {
#pragma unroll
    for (int b = 0; b < 4; b++) {
        A[b][0] = cvt_tf32(C[b][0]);
        A[b][1] = cvt_tf32(C[b][2]);
        A[b][2] = cvt_tf32(C[b][1]);
        A[b][3] = cvt_tf32(C[b][3]);
    }
}

__device__ __forceinline__ void lrelu16(float C[4][4]) {
#pragma unroll
    for (int b = 0; b < 4; b++)
#pragma unroll
        for (int r = 0; r < 4; r++) C[b][r] = lrelu(C[b][r]);
}

// load a tau-space 32-vector pair (rows rA, rB) into A-frags
__device__ __forceinline__ void gather_a(const float* __restrict__ base0,
                                         const float* __restrict__ base1,
                                         unsigned A[4][4], int q) {
#pragma unroll
    for (int b = 0; b < 4; b++) {
        float2 v0 = *(const float2*)(base0 + 8 * b + 2 * q);
        float2 v1 = *(const float2*)(base1 + 8 * b + 2 * q);
        A[b][0] = cvt_tf32(v0.x); A[b][2] = cvt_tf32(v0.y);
        A[b][1] = cvt_tf32(v1.x); A[b][3] = cvt_tf32(v1.y);
    }
}

// fill B-fragments into smem: dst[(kb*4+nb)*32+lane] = {W[8kb+q][colL], W[8kb+q+4][colL]}
// colL = 8*nb + tau_inner(lane>>2); W row-major [rows][32]
__device__ void fill_bfrag(uint2* dst, const float* __restrict__ W, int kblocks) {
    for (int i = threadIdx.x; i < kblocks * 4 * 32; i += blockDim.x) {
        int lane = i & 31, pi = i >> 5;
        int kb = pi >> 2, nb = pi & 3;
        int q = lane & 3, u = lane >> 2;
        int colL = 8 * nb + ((u & 1) ? (u >> 1) + 4 : (u >> 1));
        int r0 = 8 * kb + q;
        uint2 v;
        v.x = cvt_tf32(W[r0 * 32 + colL]);
        v.y = cvt_tf32(W[(r0 + 4) * 32 + colL]);
        dst[pi * 32 + lane] = v;
    }
}

// ---------------- init ----------------
__global__ void kinit() {
    int i = blockIdx.x * blockDim.x + threadIdx.x;
    if (i < N_NODES * D) { g_s0[i] = 0.f; g_s1[i] = 0.f; }
    if (i < N_NODES)     { g_mi[i] = (int)0x80000000; g_dsum[i] = 0.f; }
}

// ---------------- K0: t0 = TMLP0(h0) (rank-1 folded) -> scatter s0 ----------------
__global__ __launch_bounds__(256)
void k0(const float* __restrict__ ea, const int* __restrict__ idx,
        const float* __restrict__ w_in, const float* __restrict__ b_in,
        const float* __restrict__ tw1, const float* __restrict__ tb1,
        const float* __restrict__ tw2, const float* __restrict__ tb2) {
    __shared__ uint2 sT2[512];
    __shared__ __align__(8) float sPT[32], sQT[32], sTB2[32];
    int t = threadIdx.x;
    if (t < 32) {
        int cL = tau_(t);
        float p = 0.f, qv = 0.f;
        for (int k = 0; k < 32; ++k) {
            p  = fmaf(w_in[k], tw1[k * 32 + cL], p);
            qv = fmaf(b_in[k], tw1[k * 32 + cL], qv);
        }
        sPT[t] = p; sQT[t] = qv + tb1[cL];
        sTB2[t] = tb2[cL];
    }
    fill_bfrag(sT2, tw2, 4);
    __syncthreads();

    int lane = t & 31, warp = t >> 5;
    int q = lane & 3, rA = lane >> 2;
    for (int tile = blockIdx.x * 8 + warp; tile < NTILES; tile += gridDim.x * 8) {
        int e0 = tile * 16;
        int eA = e0 + rA, eB = eA + 8;
        float aA = ea[eA], aB = ea[eB];
        int nA = idx[eA], nB = idx[eB];

        unsigned A[4][4];
#pragma unroll
        for (int nb = 0; nb < 4; nb++) {
            int u0 = 8 * nb + 2 * q;
            float2 P = *(const float2*)&sPT[u0];
            float2 Q = *(const float2*)&sQT[u0];
            float z0 = lrelu(fmaf(aA, P.x, Q.x)), z1 = lrelu(fmaf(aA, P.y, Q.y));
            float z2 = lrelu(fmaf(aB, P.x, Q.x)), z3 = lrelu(fmaf(aB, P.y, Q.y));
            A[nb][0] = cvt_tf32(z0); A[nb][1] = cvt_tf32(z2);
            A[nb][2] = cvt_tf32(z1); A[nb][3] = cvt_tf32(z3);
        }
        float C[4][4];
#pragma unroll
        for (int nb = 0; nb < 4; nb++) {
            int u0 = 8 * nb + 2 * q;
            float2 B2 = *(const float2*)&sTB2[u0];
            C[nb][0] = B2.x; C[nb][1] = B2.y; C[nb][2] = B2.x; C[nb][3] = B2.y;
        }
        mm_tile(A, sT2, C, lane);

        float* pA = g_s0 + (size_t)nA * 32;
        float* pB = g_s0 + (size_t)nB * 32;
#pragma unroll
        for (int nb = 0; nb < 4; nb++) {
            int u0 = 8 * nb + 2 * q;
            red_add2(pA + u0, C[nb][0], C[nb][1]);
            red_add2(pB + u0, C[nb][2], C[nb][3]);
        }
    }
}

// ---------------- K1: h1 = UPD0(h0,s0[idx]); t1 = TMLP1(h1) -> scatter s1; store h1 --
__global__ __launch_bounds__(256)
void k1(const float* __restrict__ ea, const int* __restrict__ idx,
        const float* __restrict__ w_in, const float* __restrict__ b_in,
        const float* __restrict__ tw1, const float* __restrict__ tb1,
        const float* __restrict__ tw2, const float* __restrict__ tb2,
        const float* __restrict__ uw1, const float* __restrict__ ub1,
        const float* __restrict__ uw2, const float* __restrict__ ub2) {
    __shared__ uint2 sU1b[512], sU2[512], sT1[512], sT2[512];
    __shared__ __align__(8) float sPU[32], sQU[32], sUB2[32], sTB1[32], sTB2[32];
    int t = threadIdx.x;
    if (t < 32) {
        int cL = tau_(t);
        float p = 0.f, qv = 0.f;
        for (int k = 0; k < 32; ++k) {
            p  = fmaf(w_in[k], uw1[k * 32 + cL], p);
            qv = fmaf(b_in[k], uw1[k * 32 + cL], qv);
        }
        sPU[t] = p; sQU[t] = qv + ub1[cL];
        sUB2[t] = ub2[cL];
        sTB1[t] = tb1[32 + cL];
        sTB2[t] = tb2[32 + cL];
    }
    fill_bfrag(sU1b, uw1 + 1024, 4);   // uw1[0] rows 32..63
    fill_bfrag(sU2,  uw2, 4);          // uw2[0]
    fill_bfrag(sT1,  tw1 + 1024, 4);   // tw1[1]
    fill_bfrag(sT2,  tw2 + 1024, 4);   // tw2[1]
    __syncthreads();

    int lane = t & 31, warp = t >> 5;
    int q = lane & 3, rA = lane >> 2;
    for (int tile = blockIdx.x * 8 + warp; tile < NTILES; tile += gridDim.x * 8) {
        int e0 = tile * 16;
        int eA = e0 + rA, eB = eA + 8;
        float aA = ea[eA], aB = ea[eB];
        int nA = idx[eA], nB = idx[eB];

        unsigned A[4][4];
        gather_a(g_s0 + (size_t)nA * 32, g_s0 + (size_t)nB * 32, A, q);

        float C[4][4];
#pragma unroll
        for (int nb = 0; nb < 4; nb++) {
            int u0 = 8 * nb + 2 * q;
            float2 P = *(const float2*)&sPU[u0];
            float2 Q = *(const float2*)&sQU[u0];
            C[nb][0] = fmaf(aA, P.x, Q.x); C[nb][1] = fmaf(aA, P.y, Q.y);
            C[nb][2] = fmaf(aB, P.x, Q.x); C[nb][3] = fmaf(aB, P.y, Q.y);
        }
        mm_tile(A, sU1b, C, lane);
        lrelu16(C);
        c2a(C, A);

        float H[4][4];
#pragma unroll
        for (int nb = 0; nb < 4; nb++) {
            int u0 = 8 * nb + 2 * q;
            float2 B2 = *(const float2*)&sUB2[u0];
            H[nb][0] = B2.x; H[nb][1] = B2.y; H[nb][2] = B2.x; H[nb][3] = B2.y;
        }
        mm_tile(A, sU2, H, lane);

        // persist h1 (tau-space, [E][32])
        float* hA = g_h1 + (size_t)eA * 32;
        float* hB = g_h1 + (size_t)eB * 32;
#pragma unroll
        for (int nb = 0; nb < 4; nb++) {
            int u0 = 8 * nb + 2 * q;
            *(float2*)(hA + u0) = make_float2(H[nb][0], H[nb][1]);
            *(float2*)(hB + u0) = make_float2(H[nb][2], H[nb][3]);
        }

        // T layer 1
        c2a(H, A);
#pragma unroll
        for (int nb = 0; nb < 4; nb++) {
            int u0 = 8 * nb + 2 * q;
            float2 B2 = *(const float2*)&sTB1[u0];
            C[nb][0] = B2.x; C[nb][1] = B2.y; C[nb][2] = B2.x; C[nb][3] = B2.y;
        }
        mm_tile(A, sT1, C, lane);
        lrelu16(C);
        c2a(C, A);
#pragma unroll
        for (int nb = 0; nb < 4; nb++) {
            int u0 = 8 * nb + 2 * q;
            float2 B2 = *(const float2*)&sTB2[u0];
            C[nb][0] = B2.x; C[nb][1] = B2.y; C[nb][2] = B2.x; C[nb][3] = B2.y;
        }
        mm_tile(A, sT2, C, lane);

        float* pA = g_s1 + (size_t)nA * 32;
        float* pB = g_s1 + (size_t)nB * 32;
#pragma unroll
        for (int nb = 0; nb < 4; nb++) {
            int u0 = 8 * nb + 2 * q;
            red_add2(pA + u0, C[nb][0], C[nb][1]);
            red_add2(pB + u0, C[nb][2], C[nb][3]);
        }
    }
}

// ---------------- K2: h2 = UPD1(h1,s1[idx]); head -> logits; atomicMax ------------
__global__ __launch_bounds__(256)
void k2(const float* __restrict__ ea, const int* __restrict__ idx,
        const float* __restrict__ w_in, const float* __restrict__ b_in,
        const float* __restrict__ uw1, const float* __restrict__ ub1,
        const float* __restrict__ uw2, const float* __restrict__ ub2,
        const float* __restrict__ hw1, const float* __restrict__ hb1,
        const float* __restrict__ hw2, const float* __restrict__ hb2,
        const float* __restrict__ hw3, const float* __restrict__ hb3) {
    __shared__ uint2 sU1[1024];                 // uw1[1] full 64x32 (8 kblocks)
    __shared__ uint2 sU2[512], sH1b[512], sH2[512];
    __shared__ __align__(8) float sUB1[32], sUB2[32], sPH[32], sQH[32], sHB2[32], sH3[32];
    __shared__ float sHB3;
    int t = threadIdx.x;
    const float* u1 = uw1 + 2048;               // uw1[1]
    if (t < 32) {
        int cL = tau_(t);
        float p = 0.f, qv = 0.f;
        for (int k = 0; k < 32; ++k) {
            p  = fmaf(w_in[k], hw1[k * 32 + cL], p);
            qv = fmaf(b_in[k], hw1[k * 32 + cL], qv);
        }
        sPH[t] = p; sQH[t] = qv + hb1[cL];
        sUB1[t] = ub1[32 + cL];
        sUB2[t] = ub2[32 + cL];
        sHB2[t] = hb2[cL];
        sH3[t]  = hw3[cL];
    }
    if (t == 0) sHB3 = hb3[0];
    fill_bfrag(sU1,  u1, 8);           // 64 rows: kb0..3 = h-part, kb4..7 = s-part
    fill_bfrag(sU2,  uw2 + 1024, 4);   // uw2[1]
    fill_bfrag(sH1b, hw1 + 1024, 4);   // hw1 rows 32..63
    fill_bfrag(sH2,  hw2, 4);
    __syncthreads();

    int lane = t & 31, warp = t >> 5;
    int q = lane & 3, rA = lane >> 2;
    for (int tile = blockIdx.x * 8 + warp; tile < NTILES; tile += gridDim.x * 8) {
        int e0 = tile * 16;
        int eA = e0 + rA, eB = eA + 8;
        float aA = ea[eA], aB = ea[eB];
        int nA = idx[eA], nB = idx[eB];

        unsigned Ah[4][4], As[4][4];
        gather_a(g_h1 + (size_t)eA * 32, g_h1 + (size_t)eB * 32, Ah, q);
        gather_a(g_s1 + (size_t)nA * 32, g_s1 + (size_t)nB * 32, As, q);

        float C[4][4];
#pragma unroll
        for (int nb = 0; nb < 4; nb++) {
            int u0 = 8 * nb + 2 * q;
            float2 B2 = *(const float2*)&sUB1[u0];
            C[nb][0] = B2.x; C[nb][1] = B2.y; C[nb][2] = B2.x; C[nb][3] = B2.y;
        }
        mm_tile(Ah, sU1, C, lane);
        mm_tile(As, sU1 + 16 * 32, C, lane);
        lrelu16(C);

        unsigned A[4][4];
        c2a(C, A);
        float H[4][4];
#pragma unroll
        for (int nb = 0; nb < 4; nb++) {
            int u0 = 8 * nb + 2 * q;
            float2 B2 = *(const float2*)&sUB2[u0];
            H[nb][0] = B2.x; H[nb][1] = B2.y; H[nb][2] = B2.x; H[nb][3] = B2.y;
        }
        mm_tile(A, sU2, H, lane);

        // v1 = lrelu(a*PH + QH + h2 @ H1b)
        c2a(H, A);
#pragma unroll
        for (int nb = 0; nb < 4; nb++) {
            int u0 = 8 * nb + 2 * q;
            float2 P = *(const float2*)&sPH[u0];
            float2 Q = *(const float2*)&sQH[u0];
            C[nb][0] = fmaf(aA, P.x, Q.x); C[nb][1] = fmaf(aA, P.y, Q.y);
            C[nb][2] = fmaf(aB, P.x, Q.x); C[nb][3] = fmaf(aB, P.y, Q.y);
        }
        mm_tile(A, sH1b, C, lane);
        lrelu16(C);
        c2a(C, A);
#pragma unroll
        for (int nb = 0; nb < 4; nb++) {
            int u0 = 8 * nb + 2 * q;
            float2 B2 = *(const float2*)&sHB2[u0];
            C[nb][0] = B2.x; C[nb][1] = B2.y; C[nb][2] = B2.x; C[nb][3] = B2.y;
        }
        mm_tile(A, sH2, C, lane);
        lrelu16(C);

        // head dot + row reduce
        float dA = 0.f, dB = 0.f;
#pragma unroll
        for (int nb = 0; nb < 4; nb++) {
            int u0 = 8 * nb + 2 * q;
            float2 h3 = *(const float2*)&sH3[u0];
            dA = fmaf(C[nb][0], h3.x, dA); dA = fmaf(C[nb][1], h3.y, dA);
            dB = fmaf(C[nb][2], h3.x, dB); dB = fmaf(C[nb][3], h3.y, dB);
        }
        dA += __shfl_xor_sync(0xffffffffu, dA, 1);
        dA += __shfl_xor_sync(0xffffffffu, dA, 2);
        dB += __shfl_xor_sync(0xffffffffu, dB, 1);
        dB += __shfl_xor_sync(0xffffffffu, dB, 2);

        if (q == 0) {
            float vA = dA + sHB3, vB = dB + sHB3;
            g_vals[eA] = vA;
            g_vals[eB] = vB;
            atomicMax(&g_mi[nA], fenc(vA));
            atomicMax(&g_mi[nB], fenc(vB));
        }
    }
}

// ---------------- K3 / K4: softmax ----------------
__global__ void k3(const int* __restrict__ idx, float* __restrict__ out) {
    int e = blockIdx.x * blockDim.x + threadIdx.x;
    if (e >= E_EDGES) return;
    int node = idx[e];
    float m = fdec(g_mi[node]);
    float ex = expf(g_vals[e] - m);
    red_add1(&g_dsum[node], ex);
    out[e] = ex;
}
__global__ void k4(const int* __restrict__ idx, float* __restrict__ out) {
    int e = blockIdx.x * blockDim.x + threadIdx.x;
    if (e >= E_EDGES) return;
    out[e] = out[e] / g_dsum[idx[e]];
}

// ---------------- launcher ----------------
extern "C" void kernel_launch(void* const* d_in, const int* in_sizes, int n_in,
                              void* d_out, int out_size) {
    const float* ea   = (const float*)d_in[0];
    const int*   eidx = (const int*)d_in[1];
    const float* w_in = (const float*)d_in[2];
    const float* b_in = (const float*)d_in[3];
    const float* tw1  = (const float*)d_in[4];
    const float* tb1  = (const float*)d_in[5];
    const float* tw2  = (const float*)d_in[6];
    const float* tb2  = (const float*)d_in[7];
    const float* uw1  = (const float*)d_in[8];
    const float* ub1  = (const float*)d_in[9];
    const float* uw2  = (const float*)d_in[10];
    const float* ub2  = (const float*)d_in[11];
    const float* hw1  = (const float*)d_in[12];
    const float* hb1  = (const float*)d_in[13];
    const float* hw2  = (const float*)d_in[14];
    const float* hb2  = (const float*)d_in[15];
    const float* hw3  = (const float*)d_in[16];
    const float* hb3  = (const float*)d_in[17];
    float* out = (float*)d_out;

    const int TB = 256;
    kinit<<<(N_NODES * D + TB - 1) / TB, TB>>>();
    const int GB = 2048;   // grid-stride over warp-tiles (8 tiles / block / iter)
    k0<<<GB, 256>>>(ea, eidx, w_in, b_in, tw1, tb1, tw2, tb2);
    k1<<<GB, 256>>>(ea, eidx, w_in, b_in, tw1, tb1, tw2, tb2, uw1, ub1, uw2, ub2);
    k2<<<GB, 256>>>(ea, eidx, w_in, b_in, uw1, ub1, uw2, ub2,
                    hw1, hb1, hw2, hb2, hw3, hb3);
    int gb = (E_EDGES + TB - 1) / TB;
    k3<<<gb, TB>>>(eidx, out);
    k4<<<gb, TB>>>(eidx, out);
}

// round 4
// speedup vs baseline: 3.9148x; 1.1864x over previous
#include <cuda_runtime.h>

#define E_EDGES 2000000
#define N_NODES 50000
#define D 32
#define NTILES (E_EDGES / 16)

// ---------------- scratch ----------------
__device__ float g_s0[N_NODES * D];            // segment sums layer 0 (tau-space)
__device__ float g_s1[N_NODES * D];            // segment sums layer 1 (tau-space)
__device__ float g_h1[(size_t)E_EDGES * D];    // h after layer 0 (tau-space, [E][32])
__device__ float g_dsum[N_NODES];              // softmax denominators

__device__ __forceinline__ float lrelu(float x) { return fmaxf(x, 0.01f * x); }
__device__ __forceinline__ void red_add2(float* p, float a, float b) {
    asm volatile("red.global.add.v2.f32 [%0], {%1,%2};" :: "l"(p), "f"(a), "f"(b) : "memory");
}
__device__ __forceinline__ void red_add1(float* p, float v) {
    asm volatile("red.global.add.f32 [%0], %1;" :: "l"(p), "f"(v) : "memory");
}

// tau permutation within each 8-block: tau(2q)=q, tau(2q+1)=q+4
__device__ __forceinline__ int tau_(int u) {
    int b = u & ~7, v = u & 7;
    return b + ((v & 1) ? (v >> 1) + 4 : (v >> 1));
}

__device__ __forceinline__ unsigned cvt_tf32(float f) {
    unsigned r; asm("cvt.rna.tf32.f32 %0, %1;" : "=r"(r) : "f"(f)); return r;
}

__device__ __forceinline__ void mma8(float& c0, float& c1, float& c2, float& c3,
                                     unsigned a0, unsigned a1, unsigned a2, unsigned a3,
                                     unsigned b0, unsigned b1) {
    asm("mma.sync.aligned.m16n8k8.row.col.f32.tf32.tf32.f32 "
        "{%0,%1,%2,%3},{%4,%5,%6,%7},{%8,%9},{%0,%1,%2,%3};"
        : "+f"(c0), "+f"(c1), "+f"(c2), "+f"(c3)
        : "r"(a0), "r"(a1), "r"(a2), "r"(a3), "r"(b0), "r"(b1));
}

// C[16,32] += A[16,32] @ W   (4 kblocks x 4 nblocks)
__device__ __forceinline__ void mm_tile(const unsigned A[4][4], const uint2* sB,
                                        float C[4][4], int lane) {
#pragma unroll
    for (int kb = 0; kb < 4; kb++)
#pragma unroll
        for (int nb = 0; nb < 4; nb++) {
            uint2 b = sB[(kb * 4 + nb) * 32 + lane];
            mma8(C[nb][0], C[nb][1], C[nb][2], C[nb][3],
                 A[kb][0], A[kb][1], A[kb][2], A[kb][3], b.x, b.y);
        }
}

// chain: C-frag (tau-space) -> A-frag of next matmul. (a0,a1,a2,a3)=(c0,c2,c1,c3)
__device__ __forceinline__ void c2a(const float C[4][4], unsigned A[4][4]) {
#pragma unroll
    for (int b = 0; b < 4; b++) {
        A[b][0] = cvt_tf32(C[b][0]);
        A[b][1] = cvt_tf32(C[b][2]);
        A[b][2] = cvt_tf32(C[b][1]);
        A[b][3] = cvt_tf32(C[b][3]);
    }
}

__device__ __forceinline__ void lrelu16(float C[4][4]) {
#pragma unroll
    for (int b = 0; b < 4; b++)
#pragma unroll
        for (int r = 0; r < 4; r++) C[b][r] = lrelu(C[b][r]);
}

// load a tau-space 32-vector pair (rows rA, rB) into A-frags
__device__ __forceinline__ void gather_a(const float* __restrict__ base0,
                                         const float* __restrict__ base1,
                                         unsigned A[4][4], int q) {
#pragma unroll
    for (int b = 0; b < 4; b++) {
        float2 v0 = *(const float2*)(base0 + 8 * b + 2 * q);
        float2 v1 = *(const float2*)(base1 + 8 * b + 2 * q);
        A[b][0] = cvt_tf32(v0.x); A[b][2] = cvt_tf32(v0.y);
        A[b][1] = cvt_tf32(v1.x); A[b][3] = cvt_tf32(v1.y);
    }
}

// fill B-fragments into smem: dst[(kb*4+nb)*32+lane] = {W[8kb+q][colL], W[8kb+q+4][colL]}
__device__ void fill_bfrag(uint2* dst, const float* __restrict__ W, int kblocks) {
    for (int i = threadIdx.x; i < kblocks * 4 * 32; i += blockDim.x) {
        int lane = i & 31, pi = i >> 5;
        int kb = pi >> 2, nb = pi & 3;
        int q = lane & 3, u = lane >> 2;
        int colL = 8 * nb + ((u & 1) ? (u >> 1) + 4 : (u >> 1));
        int r0 = 8 * kb + q;
        uint2 v;
        v.x = cvt_tf32(W[r0 * 32 + colL]);
        v.y = cvt_tf32(W[(r0 + 4) * 32 + colL]);
        dst[pi * 32 + lane] = v;
    }
}

// ---------------- init ----------------
__global__ void kinit() {
    int i = blockIdx.x * blockDim.x + threadIdx.x;
    if (i < N_NODES * D) { g_s0[i] = 0.f; g_s1[i] = 0.f; }
    if (i < N_NODES)     { g_dsum[i] = 0.f; }
}

// ---------------- K0: t0 = TMLP0(h0) (rank-1 folded) -> scatter s0 ----------------
__global__ __launch_bounds__(256, 2)
void k0(const float* __restrict__ ea, const int* __restrict__ idx,
        const float* __restrict__ w_in, const float* __restrict__ b_in,
        const float* __restrict__ tw1, const float* __restrict__ tb1,
        const float* __restrict__ tw2, const float* __restrict__ tb2) {
    __shared__ uint2 sT2[512];
    __shared__ __align__(8) float sPT[32], sQT[32], sTB2[32];
    int t = threadIdx.x;
    if (t < 32) {
        int cL = tau_(t);
        float p = 0.f, qv = 0.f;
        for (int k = 0; k < 32; ++k) {
            p  = fmaf(w_in[k], tw1[k * 32 + cL], p);
            qv = fmaf(b_in[k], tw1[k * 32 + cL], qv);
        }
        sPT[t] = p; sQT[t] = qv + tb1[cL];
        sTB2[t] = tb2[cL];
    }
    fill_bfrag(sT2, tw2, 4);
    __syncthreads();

    int lane = t & 31, warp = t >> 5;
    int q = lane & 3, rA = lane >> 2;
    for (int tile = blockIdx.x * 8 + warp; tile < NTILES; tile += gridDim.x * 8) {
        int e0 = tile * 16;
        int eA = e0 + rA, eB = eA + 8;
        float aA = ea[eA], aB = ea[eB];
        int nA = idx[eA], nB = idx[eB];

        unsigned A[4][4];
#pragma unroll
        for (int nb = 0; nb < 4; nb++) {
            int u0 = 8 * nb + 2 * q;
            float2 P = *(const float2*)&sPT[u0];
            float2 Q = *(const float2*)&sQT[u0];
            float z0 = lrelu(fmaf(aA, P.x, Q.x)), z1 = lrelu(fmaf(aA, P.y, Q.y));
            float z2 = lrelu(fmaf(aB, P.x, Q.x)), z3 = lrelu(fmaf(aB, P.y, Q.y));
            A[nb][0] = cvt_tf32(z0); A[nb][1] = cvt_tf32(z2);
            A[nb][2] = cvt_tf32(z1); A[nb][3] = cvt_tf32(z3);
        }
        float C[4][4];
#pragma unroll
        for (int nb = 0; nb < 4; nb++) {
            int u0 = 8 * nb + 2 * q;
            float2 B2 = *(const float2*)&sTB2[u0];
            C[nb][0] = B2.x; C[nb][1] = B2.y; C[nb][2] = B2.x; C[nb][3] = B2.y;
        }
        mm_tile(A, sT2, C, lane);

        float* pA = g_s0 + (size_t)nA * 32;
        float* pB = g_s0 + (size_t)nB * 32;
#pragma unroll
        for (int nb = 0; nb < 4; nb++) {
            int u0 = 8 * nb + 2 * q;
            red_add2(pA + u0, C[nb][0], C[nb][1]);
            red_add2(pB + u0, C[nb][2], C[nb][3]);
        }
    }
}

// ---------------- K1: h1 = UPD0(h0,s0[idx]); t1 = TMLP1(h1) -> scatter s1; store h1 --
__global__ __launch_bounds__(256, 2)
void k1(const float* __restrict__ ea, const int* __restrict__ idx,
        const float* __restrict__ w_in, const float* __restrict__ b_in,
        const float* __restrict__ tw1, const float* __restrict__ tb1,
        const float* __restrict__ tw2, const float* __restrict__ tb2,
        const float* __restrict__ uw1, const float* __restrict__ ub1,
        const float* __restrict__ uw2, const float* __restrict__ ub2) {
    __shared__ uint2 sU1b[512], sU2[512], sT1[512], sT2[512];
    __shared__ __align__(8) float sPU[32], sQU[32], sUB2[32], sTB1[32], sTB2[32];
    int t = threadIdx.x;
    if (t < 32) {
        int cL = tau_(t);
        float p = 0.f, qv = 0.f;
        for (int k = 0; k < 32; ++k) {
            p  = fmaf(w_in[k], uw1[k * 32 + cL], p);
            qv = fmaf(b_in[k], uw1[k * 32 + cL], qv);
        }
        sPU[t] = p; sQU[t] = qv + ub1[cL];
        sUB2[t] = ub2[cL];
        sTB1[t] = tb1[32 + cL];
        sTB2[t] = tb2[32 + cL];
    }
    fill_bfrag(sU1b, uw1 + 1024, 4);   // uw1[0] rows 32..63
    fill_bfrag(sU2,  uw2, 4);          // uw2[0]
    fill_bfrag(sT1,  tw1 + 1024, 4);   // tw1[1]
    fill_bfrag(sT2,  tw2 + 1024, 4);   // tw2[1]
    __syncthreads();

    int lane = t & 31, warp = t >> 5;
    int q = lane & 3, rA = lane >> 2;
    for (int tile = blockIdx.x * 8 + warp; tile < NTILES; tile += gridDim.x * 8) {
        int e0 = tile * 16;
        int eA = e0 + rA, eB = eA + 8;
        float aA = ea[eA], aB = ea[eB];
        int nA = idx[eA], nB = idx[eB];

        unsigned A[4][4];
        gather_a(g_s0 + (size_t)nA * 32, g_s0 + (size_t)nB * 32, A, q);

        float C[4][4];
#pragma unroll
        for (int nb = 0; nb < 4; nb++) {
            int u0 = 8 * nb + 2 * q;
            float2 P = *(const float2*)&sPU[u0];
            float2 Q = *(const float2*)&sQU[u0];
            C[nb][0] = fmaf(aA, P.x, Q.x); C[nb][1] = fmaf(aA, P.y, Q.y);
            C[nb][2] = fmaf(aB, P.x, Q.x); C[nb][3] = fmaf(aB, P.y, Q.y);
        }
        mm_tile(A, sU1b, C, lane);
        lrelu16(C);
        c2a(C, A);

        float H[4][4];
#pragma unroll
        for (int nb = 0; nb < 4; nb++) {
            int u0 = 8 * nb + 2 * q;
            float2 B2 = *(const float2*)&sUB2[u0];
            H[nb][0] = B2.x; H[nb][1] = B2.y; H[nb][2] = B2.x; H[nb][3] = B2.y;
        }
        mm_tile(A, sU2, H, lane);

        // persist h1 (tau-space, [E][32])
        float* hA = g_h1 + (size_t)eA * 32;
        float* hB = g_h1 + (size_t)eB * 32;
#pragma unroll
        for (int nb = 0; nb < 4; nb++) {
            int u0 = 8 * nb + 2 * q;
            *(float2*)(hA + u0) = make_float2(H[nb][0], H[nb][1]);
            *(float2*)(hB + u0) = make_float2(H[nb][2], H[nb][3]);
        }

        // T layer 1
        c2a(H, A);
#pragma unroll
        for (int nb = 0; nb < 4; nb++) {
            int u0 = 8 * nb + 2 * q;
            float2 B2 = *(const float2*)&sTB1[u0];
            C[nb][0] = B2.x; C[nb][1] = B2.y; C[nb][2] = B2.x; C[nb][3] = B2.y;
        }
        mm_tile(A, sT1, C, lane);
        lrelu16(C);
        c2a(C, A);
#pragma unroll
        for (int nb = 0; nb < 4; nb++) {
            int u0 = 8 * nb + 2 * q;
            float2 B2 = *(const float2*)&sTB2[u0];
            C[nb][0] = B2.x; C[nb][1] = B2.y; C[nb][2] = B2.x; C[nb][3] = B2.y;
        }
        mm_tile(A, sT2, C, lane);

        float* pA = g_s1 + (size_t)nA * 32;
        float* pB = g_s1 + (size_t)nB * 32;
#pragma unroll
        for (int nb = 0; nb < 4; nb++) {
            int u0 = 8 * nb + 2 * q;
            red_add2(pA + u0, C[nb][0], C[nb][1]);
            red_add2(pB + u0, C[nb][2], C[nb][3]);
        }
    }
}

// ---------------- K2: h2 = UPD1(h1,s1[idx]); head -> exp(logit); red denom --------
__global__ __launch_bounds__(256, 2)
void k2(const float* __restrict__ ea, const int* __restrict__ idx,
        const float* __restrict__ w_in, const float* __restrict__ b_in,
        const float* __restrict__ uw1, const float* __restrict__ ub1,
        const float* __restrict__ uw2, const float* __restrict__ ub2,
        const float* __restrict__ hw1, const float* __restrict__ hb1,
        const float* __restrict__ hw2, const float* __restrict__ hb2,
        const float* __restrict__ hw3, const float* __restrict__ hb3,
        float* __restrict__ out) {
    __shared__ uint2 sU1[1024];                 // uw1[1] full 64x32 (8 kblocks)
    __shared__ uint2 sU2[512], sH1b[512], sH2[512];
    __shared__ __align__(8) float sUB1[32], sUB2[32], sPH[32], sQH[32], sHB2[32], sH3[32];
    __shared__ float sHB3;
    int t = threadIdx.x;
    const float* u1 = uw1 + 2048;               // uw1[1]
    if (t < 32) {
        int cL = tau_(t);
        float p = 0.f, qv = 0.f;
        for (int k = 0; k < 32; ++k) {
            p  = fmaf(w_in[k], hw1[k * 32 + cL], p);
            qv = fmaf(b_in[k], hw1[k * 32 + cL], qv);
        }
        sPH[t] = p; sQH[t] = qv + hb1[cL];
        sUB1[t] = ub1[32 + cL];
        sUB2[t] = ub2[32 + cL];
        sHB2[t] = hb2[cL];
        sH3[t]  = hw3[cL];
    }
    if (t == 0) sHB3 = hb3[0];
    fill_bfrag(sU1,  u1, 8);           // 64 rows: kb0..3 = h-part, kb4..7 = s-part
    fill_bfrag(sU2,  uw2 + 1024, 4);   // uw2[1]
    fill_bfrag(sH1b, hw1 + 1024, 4);   // hw1 rows 32..63
    fill_bfrag(sH2,  hw2, 4);
    __syncthreads();

    int lane = t & 31, warp = t >> 5;
    int q = lane & 3, rA = lane >> 2;
    for (int tile = blockIdx.x * 8 + warp; tile < NTILES; tile += gridDim.x * 8) {
        int e0 = tile * 16;
        int eA = e0 + rA, eB = eA + 8;
        float aA = ea[eA], aB = ea[eB];
        int nA = idx[eA], nB = idx[eB];

        // pass 1: C = UB1 + h1 @ U1[h-part]   (one gather fragment live at a time)
        float C[4][4];
#pragma unroll
        for (int nb = 0; nb < 4; nb++) {
            int u0 = 8 * nb + 2 * q;
            float2 B2 = *(const float2*)&sUB1[u0];
            C[nb][0] = B2.x; C[nb][1] = B2.y; C[nb][2] = B2.x; C[nb][3] = B2.y;
        }
        unsigned A[4][4];
        gather_a(g_h1 + (size_t)eA * 32, g_h1 + (size_t)eB * 32, A, q);
        mm_tile(A, sU1, C, lane);
        // pass 2: C += s1 @ U1[s-part]
        gather_a(g_s1 + (size_t)nA * 32, g_s1 + (size_t)nB * 32, A, q);
        mm_tile(A, sU1 + 16 * 32, C, lane);
        lrelu16(C);

        c2a(C, A);
        float H[4][4];
#pragma unroll
        for (int nb = 0; nb < 4; nb++) {
            int u0 = 8 * nb + 2 * q;
            float2 B2 = *(const float2*)&sUB2[u0];
            H[nb][0] = B2.x; H[nb][1] = B2.y; H[nb][2] = B2.x; H[nb][3] = B2.y;
        }
        mm_tile(A, sU2, H, lane);

        // v1 = lrelu(a*PH + QH + h2 @ H1b)
        c2a(H, A);
#pragma unroll
        for (int nb = 0; nb < 4; nb++) {
            int u0 = 8 * nb + 2 * q;
            float2 P = *(const float2*)&sPH[u0];
            float2 Q = *(const float2*)&sQH[u0];
            C[nb][0] = fmaf(aA, P.x, Q.x); C[nb][1] = fmaf(aA, P.y, Q.y);
            C[nb][2] = fmaf(aB, P.x, Q.x); C[nb][3] = fmaf(aB, P.y, Q.y);
        }
        mm_tile(A, sH1b, C, lane);
        lrelu16(C);
        c2a(C, A);
#pragma unroll
        for (int nb = 0; nb < 4; nb++) {
            int u0 = 8 * nb + 2 * q;
            float2 B2 = *(const float2*)&sHB2[u0];
            C[nb][0] = B2.x; C[nb][1] = B2.y; C[nb][2] = B2.x; C[nb][3] = B2.y;
        }
        mm_tile(A, sH2, C, lane);
        lrelu16(C);

        // head dot + row reduce
        float dA = 0.f, dB = 0.f;
#pragma unroll
        for (int nb = 0; nb < 4; nb++) {
            int u0 = 8 * nb + 2 * q;
            float2 h3 = *(const float2*)&sH3[u0];
            dA = fmaf(C[nb][0], h3.x, dA); dA = fmaf(C[nb][1], h3.y, dA);
            dB = fmaf(C[nb][2], h3.x, dB); dB = fmaf(C[nb][3], h3.y, dB);
        }
        dA += __shfl_xor_sync(0xffffffffu, dA, 1);
        dA += __shfl_xor_sync(0xffffffffu, dA, 2);
        dB += __shfl_xor_sync(0xffffffffu, dB, 1);
        dB += __shfl_xor_sync(0xffffffffu, dB, 2);

        if (q == 0) {
            // unshifted softmax: exp(v) directly (logits bounded, fp32-safe)
            float exA = expf(dA + sHB3), exB = expf(dB + sHB3);
            out[eA] = exA;
            out[eB] = exB;
            red_add1(&g_dsum[nA], exA);
            red_add1(&g_dsum[nB], exB);
        }
    }
}

// ---------------- K4: normalize ----------------
__global__ void k4(const int* __restrict__ idx, float* __restrict__ out) {
    int e = blockIdx.x * blockDim.x + threadIdx.x;
    if (e >= E_EDGES) return;
    out[e] = out[e] / g_dsum[idx[e]];
}

// ---------------- launcher ----------------
extern "C" void kernel_launch(void* const* d_in, const int* in_sizes, int n_in,
                              void* d_out, int out_size) {
    const float* ea   = (const float*)d_in[0];
    const int*   eidx = (const int*)d_in[1];
    const float* w_in = (const float*)d_in[2];
    const float* b_in = (const float*)d_in[3];
    const float* tw1  = (const float*)d_in[4];
    const float* tb1  = (const float*)d_in[5];
    const float* tw2  = (const float*)d_in[6];
    const float* tb2  = (const float*)d_in[7];
    const float* uw1  = (const float*)d_in[8];
    const float* ub1  = (const float*)d_in[9];
    const float* uw2  = (const float*)d_in[10];
    const float* ub2  = (const float*)d_in[11];
    const float* hw1  = (const float*)d_in[12];
    const float* hb1  = (const float*)d_in[13];
    const float* hw2  = (const float*)d_in[14];
    const float* hb2  = (const float*)d_in[15];
    const float* hw3  = (const float*)d_in[16];
    const float* hb3  = (const float*)d_in[17];
    float* out = (float*)d_out;

    const int TB = 256;
    kinit<<<(N_NODES * D + TB - 1) / TB, TB>>>();
    const int GB = 2048;   // grid-stride over warp-tiles (8 tiles / block / iter)
    k0<<<GB, 256>>>(ea, eidx, w_in, b_in, tw1, tb1, tw2, tb2);
    k1<<<GB, 256>>>(ea, eidx, w_in, b_in, tw1, tb1, tw2, tb2, uw1, ub1, uw2, ub2);
    k2<<<GB, 256>>>(ea, eidx, w_in, b_in, uw1, ub1, uw2, ub2,
                    hw1, hb1, hw2, hb2, hw3, hb3, out);
    int gb = (E_EDGES + TB - 1) / TB;
    k4<<<gb, TB>>>(eidx, out);
}

// round 5
// speedup vs baseline: 4.1269x; 1.0542x over previous
#include <cuda_runtime.h>

#define E_EDGES 2000000
#define N_NODES 50000
#define D 32
#define NTILES (E_EDGES / 16)

// ---------------- scratch ----------------
__device__ float g_s0[N_NODES * D];            // segment sums layer 0 (tau-space)
__device__ float g_s1[N_NODES * D];            // segment sums layer 1 (tau-space)
__device__ float g_dsum[N_NODES];              // softmax denominators

__device__ __forceinline__ float lrelu(float x) { return fmaxf(x, 0.01f * x); }
__device__ __forceinline__ void red_add2(float* p, float a, float b) {
    asm volatile("red.global.add.v2.f32 [%0], {%1,%2};" :: "l"(p), "f"(a), "f"(b) : "memory");
}
__device__ __forceinline__ void red_add1(float* p, float v) {
    asm volatile("red.global.add.f32 [%0], %1;" :: "l"(p), "f"(v) : "memory");
}

// tau permutation within each 8-block: tau(2q)=q, tau(2q+1)=q+4
__device__ __forceinline__ int tau_(int u) {
    int b = u & ~7, v = u & 7;
    return b + ((v & 1) ? (v >> 1) + 4 : (v >> 1));
}

__device__ __forceinline__ unsigned cvt_tf32(float f) {   // weight prep only
    unsigned r; asm("cvt.rna.tf32.f32 %0, %1;" : "=r"(r) : "f"(f)); return r;
}
// hot path: raw fp32 bits; HMMA.tf32 truncates in HW
__device__ __forceinline__ unsigned bits_(float f) { return __float_as_uint(f); }

__device__ __forceinline__ void mma8(float& c0, float& c1, float& c2, float& c3,
                                     unsigned a0, unsigned a1, unsigned a2, unsigned a3,
                                     unsigned b0, unsigned b1) {
    asm("mma.sync.aligned.m16n8k8.row.col.f32.tf32.tf32.f32 "
        "{%0,%1,%2,%3},{%4,%5,%6,%7},{%8,%9},{%0,%1,%2,%3};"
        : "+f"(c0), "+f"(c1), "+f"(c2), "+f"(c3)
        : "r"(a0), "r"(a1), "r"(a2), "r"(a3), "r"(b0), "r"(b1));
}

// C[16,32] += A[16,32] @ W   (4 kblocks x 4 nblocks)
__device__ __forceinline__ void mm_tile(const unsigned A[4][4], const uint2* sB,
                                        float C[4][4], int lane) {
#pragma unroll
    for (int kb = 0; kb < 4; kb++)
#pragma unroll
        for (int nb = 0; nb < 4; nb++) {
            uint2 b = sB[(kb * 4 + nb) * 32 + lane];
            mma8(C[nb][0], C[nb][1], C[nb][2], C[nb][3],
                 A[kb][0], A[kb][1], A[kb][2], A[kb][3], b.x, b.y);
        }
}

// chain: C-frag (tau-space) -> A-frag of next matmul. (a0,a1,a2,a3)=(c0,c2,c1,c3)
__device__ __forceinline__ void c2a(const float C[4][4], unsigned A[4][4]) {
#pragma unroll
    for (int b = 0; b < 4; b++) {
        A[b][0] = bits_(C[b][0]);
        A[b][1] = bits_(C[b][2]);
        A[b][2] = bits_(C[b][1]);
        A[b][3] = bits_(C[b][3]);
    }
}

__device__ __forceinline__ void lrelu16(float C[4][4]) {
#pragma unroll
    for (int b = 0; b < 4; b++)
#pragma unroll
        for (int r = 0; r < 4; r++) C[b][r] = lrelu(C[b][r]);
}

// load a tau-space 32-vector pair (rows rA, rB) into A-frags
__device__ __forceinline__ void gather_a(const float* __restrict__ base0,
                                         const float* __restrict__ base1,
                                         unsigned A[4][4], int q) {
#pragma unroll
    for (int b = 0; b < 4; b++) {
        float2 v0 = *(const float2*)(base0 + 8 * b + 2 * q);
        float2 v1 = *(const float2*)(base1 + 8 * b + 2 * q);
        A[b][0] = bits_(v0.x); A[b][2] = bits_(v0.y);
        A[b][1] = bits_(v1.x); A[b][3] = bits_(v1.y);
    }
}

// fill B-fragments into smem: dst[(kb*4+nb)*32+lane] = {W[8kb+q][colL], W[8kb+q+4][colL]}
__device__ void fill_bfrag(uint2* dst, const float* __restrict__ W, int kblocks) {
    for (int i = threadIdx.x; i < kblocks * 4 * 32; i += blockDim.x) {
        int lane = i & 31, pi = i >> 5;
        int kb = pi >> 2, nb = pi & 3;
        int q = lane & 3, u = lane >> 2;
        int colL = 8 * nb + ((u & 1) ? (u >> 1) + 4 : (u >> 1));
        int r0 = 8 * kb + q;
        uint2 v;
        v.x = cvt_tf32(W[r0 * 32 + colL]);
        v.y = cvt_tf32(W[(r0 + 4) * 32 + colL]);
        dst[pi * 32 + lane] = v;
    }
}

// ---------------- init ----------------
__global__ void kinit() {
    int i = blockIdx.x * blockDim.x + threadIdx.x;
    if (i < N_NODES * D) { g_s0[i] = 0.f; g_s1[i] = 0.f; }
    if (i < N_NODES)     { g_dsum[i] = 0.f; }
}

// ---------------- K0: t0 = TMLP0(h0) (rank-1 folded) -> scatter s0 ----------------
__global__ __launch_bounds__(256, 2)
void k0(const float* __restrict__ ea, const int* __restrict__ idx,
        const float* __restrict__ w_in, const float* __restrict__ b_in,
        const float* __restrict__ tw1, const float* __restrict__ tb1,
        const float* __restrict__ tw2, const float* __restrict__ tb2) {
    __shared__ uint2 sT2[512];
    __shared__ __align__(8) float sPT[32], sQT[32], sTB2[32];
    int t = threadIdx.x;
    if (t < 32) {
        int cL = tau_(t);
        float p = 0.f, qv = 0.f;
        for (int k = 0; k < 32; ++k) {
            p  = fmaf(w_in[k], tw1[k * 32 + cL], p);
            qv = fmaf(b_in[k], tw1[k * 32 + cL], qv);
        }
        sPT[t] = p; sQT[t] = qv + tb1[cL];
        sTB2[t] = tb2[cL];
    }
    fill_bfrag(sT2, tw2, 4);
    __syncthreads();

    int lane = t & 31, warp = t >> 5;
    int q = lane & 3, rA = lane >> 2;
    for (int tile = blockIdx.x * 8 + warp; tile < NTILES; tile += gridDim.x * 8) {
        int e0 = tile * 16;
        int eA = e0 + rA, eB = eA + 8;
        float aA = ea[eA], aB = ea[eB];
        int nA = idx[eA], nB = idx[eB];

        unsigned A[4][4];
#pragma unroll
        for (int nb = 0; nb < 4; nb++) {
            int u0 = 8 * nb + 2 * q;
            float2 P = *(const float2*)&sPT[u0];
            float2 Q = *(const float2*)&sQT[u0];
            A[nb][0] = bits_(lrelu(fmaf(aA, P.x, Q.x)));
            A[nb][2] = bits_(lrelu(fmaf(aA, P.y, Q.y)));
            A[nb][1] = bits_(lrelu(fmaf(aB, P.x, Q.x)));
            A[nb][3] = bits_(lrelu(fmaf(aB, P.y, Q.y)));
        }
        float C[4][4];
#pragma unroll
        for (int nb = 0; nb < 4; nb++) {
            int u0 = 8 * nb + 2 * q;
            float2 B2 = *(const float2*)&sTB2[u0];
            C[nb][0] = B2.x; C[nb][1] = B2.y; C[nb][2] = B2.x; C[nb][3] = B2.y;
        }
        mm_tile(A, sT2, C, lane);

        float* pA = g_s0 + (size_t)nA * 32;
        float* pB = g_s0 + (size_t)nB * 32;
#pragma unroll
        for (int nb = 0; nb < 4; nb++) {
            int u0 = 8 * nb + 2 * q;
            red_add2(pA + u0, C[nb][0], C[nb][1]);
            red_add2(pB + u0, C[nb][2], C[nb][3]);
        }
    }
}

// ---------------- K1: h1 = UPD0(h0,s0[idx]); t1 = TMLP1(h1) -> scatter s1 ---------
__global__ __launch_bounds__(256, 2)
void k1(const float* __restrict__ ea, const int* __restrict__ idx,
        const float* __restrict__ w_in, const float* __restrict__ b_in,
        const float* __restrict__ tw1, const float* __restrict__ tb1,
        const float* __restrict__ tw2, const float* __restrict__ tb2,
        const float* __restrict__ uw1, const float* __restrict__ ub1,
        const float* __restrict__ uw2, const float* __restrict__ ub2) {
    __shared__ uint2 sU1b[512], sU2[512], sT1[512], sT2[512];
    __shared__ __align__(8) float sPU[32], sQU[32], sUB2[32], sTB1[32], sTB2[32];
    int t = threadIdx.x;
    if (t < 32) {
        int cL = tau_(t);
        float p = 0.f, qv = 0.f;
        for (int k = 0; k < 32; ++k) {
            p  = fmaf(w_in[k], uw1[k * 32 + cL], p);
            qv = fmaf(b_in[k], uw1[k * 32 + cL], qv);
        }
        sPU[t] = p; sQU[t] = qv + ub1[cL];
        sUB2[t] = ub2[cL];
        sTB1[t] = tb1[32 + cL];
        sTB2[t] = tb2[32 + cL];
    }
    fill_bfrag(sU1b, uw1 + 1024, 4);   // uw1[0] rows 32..63
    fill_bfrag(sU2,  uw2, 4);          // uw2[0]
    fill_bfrag(sT1,  tw1 + 1024, 4);   // tw1[1]
    fill_bfrag(sT2,  tw2 + 1024, 4);   // tw2[1]
    __syncthreads();

    int lane = t & 31, warp = t >> 5;
    int q = lane & 3, rA = lane >> 2;
    for (int tile = blockIdx.x * 8 + warp; tile < NTILES; tile += gridDim.x * 8) {
        int e0 = tile * 16;
        int eA = e0 + rA, eB = eA + 8;
        float aA = ea[eA], aB = ea[eB];
        int nA = idx[eA], nB = idx[eB];

        unsigned A[4][4];
        gather_a(g_s0 + (size_t)nA * 32, g_s0 + (size_t)nB * 32, A, q);

        float C[4][4];
#pragma unroll
        for (int nb = 0; nb < 4; nb++) {
            int u0 = 8 * nb + 2 * q;
            float2 P = *(const float2*)&sPU[u0];
            float2 Q = *(const float2*)&sQU[u0];
            C[nb][0] = fmaf(aA, P.x, Q.x); C[nb][1] = fmaf(aA, P.y, Q.y);
            C[nb][2] = fmaf(aB, P.x, Q.x); C[nb][3] = fmaf(aB, P.y, Q.y);
        }
        mm_tile(A, sU1b, C, lane);
        lrelu16(C);
        c2a(C, A);

        float H[4][4];
#pragma unroll
        for (int nb = 0; nb < 4; nb++) {
            int u0 = 8 * nb + 2 * q;
            float2 B2 = *(const float2*)&sUB2[u0];
            H[nb][0] = B2.x; H[nb][1] = B2.y; H[nb][2] = B2.x; H[nb][3] = B2.y;
        }
        mm_tile(A, sU2, H, lane);

        // T layer 1
        c2a(H, A);
#pragma unroll
        for (int nb = 0; nb < 4; nb++) {
            int u0 = 8 * nb + 2 * q;
            float2 B2 = *(const float2*)&sTB1[u0];
            C[nb][0] = B2.x; C[nb][1] = B2.y; C[nb][2] = B2.x; C[nb][3] = B2.y;
        }
        mm_tile(A, sT1, C, lane);
        lrelu16(C);
        c2a(C, A);
#pragma unroll
        for (int nb = 0; nb < 4; nb++) {
            int u0 = 8 * nb + 2 * q;
            float2 B2 = *(const float2*)&sTB2[u0];
            C[nb][0] = B2.x; C[nb][1] = B2.y; C[nb][2] = B2.x; C[nb][3] = B2.y;
        }
        mm_tile(A, sT2, C, lane);

        float* pA = g_s1 + (size_t)nA * 32;
        float* pB = g_s1 + (size_t)nB * 32;
#pragma unroll
        for (int nb = 0; nb < 4; nb++) {
            int u0 = 8 * nb + 2 * q;
            red_add2(pA + u0, C[nb][0], C[nb][1]);
            red_add2(pB + u0, C[nb][2], C[nb][3]);
        }
    }
}

// ---- K2: recompute h1 from s0 (L2-resident); h2 = UPD1; head; exp; red denom -----
__global__ __launch_bounds__(256, 2)
void k2(const float* __restrict__ ea, const int* __restrict__ idx,
        const float* __restrict__ w_in, const float* __restrict__ b_in,
        const float* __restrict__ uw1, const float* __restrict__ ub1,
        const float* __restrict__ uw2, const float* __restrict__ ub2,
        const float* __restrict__ hw1, const float* __restrict__ hb1,
        const float* __restrict__ hw2, const float* __restrict__ hb2,
        const float* __restrict__ hw3, const float* __restrict__ hb3,
        float* __restrict__ out) {
    __shared__ uint2 sU1[1024];                 // uw1[1] full 64x32 (8 kblocks)
    __shared__ uint2 sU2[512], sH1b[512], sH2[512];
    __shared__ uint2 sU1b0[512], sU20[512];     // layer-0 U weights for h1 recompute
    __shared__ __align__(8) float sUB1[32], sUB2[32], sPH[32], sQH[32], sHB2[32], sH3[32];
    __shared__ __align__(8) float sPU[32], sQU[32], sUB20[32];
    __shared__ float sHB3;
    int t = threadIdx.x;
    const float* u1 = uw1 + 2048;               // uw1[1]
    if (t < 32) {
        int cL = tau_(t);
        float p = 0.f, qv = 0.f, pu = 0.f, qu = 0.f;
        for (int k = 0; k < 32; ++k) {
            p  = fmaf(w_in[k], hw1[k * 32 + cL], p);
            qv = fmaf(b_in[k], hw1[k * 32 + cL], qv);
            pu = fmaf(w_in[k], uw1[k * 32 + cL], pu);
            qu = fmaf(b_in[k], uw1[k * 32 + cL], qu);
        }
        sPH[t] = p;  sQH[t] = qv + hb1[cL];
        sPU[t] = pu; sQU[t] = qu + ub1[cL];
        sUB20[t] = ub2[cL];
        sUB1[t] = ub1[32 + cL];
        sUB2[t] = ub2[32 + cL];
        sHB2[t] = hb2[cL];
        sH3[t]  = hw3[cL];
    }
    if (t == 0) sHB3 = hb3[0];
    fill_bfrag(sU1,   u1, 8);           // 64 rows: kb0..3 = h-part, kb4..7 = s-part
    fill_bfrag(sU2,   uw2 + 1024, 4);   // uw2[1]
    fill_bfrag(sH1b,  hw1 + 1024, 4);   // hw1 rows 32..63
    fill_bfrag(sH2,   hw2, 4);
    fill_bfrag(sU1b0, uw1 + 1024, 4);   // uw1[0] rows 32..63
    fill_bfrag(sU20,  uw2, 4);          // uw2[0]
    __syncthreads();

    int lane = t & 31, warp = t >> 5;
    int q = lane & 3, rA = lane >> 2;
    for (int tile = blockIdx.x * 8 + warp; tile < NTILES; tile += gridDim.x * 8) {
        int e0 = tile * 16;
        int eA = e0 + rA, eB = eA + 8;
        float aA = ea[eA], aB = ea[eB];
        int nA = idx[eA], nB = idx[eB];

        // ---- recompute h1 (layer-0 update) from s0 gather (L2) ----
        unsigned A[4][4];
        gather_a(g_s0 + (size_t)nA * 32, g_s0 + (size_t)nB * 32, A, q);
        float C[4][4];
#pragma unroll
        for (int nb = 0; nb < 4; nb++) {
            int u0 = 8 * nb + 2 * q;
            float2 P = *(const float2*)&sPU[u0];
            float2 Q = *(const float2*)&sQU[u0];
            C[nb][0] = fmaf(aA, P.x, Q.x); C[nb][1] = fmaf(aA, P.y, Q.y);
            C[nb][2] = fmaf(aB, P.x, Q.x); C[nb][3] = fmaf(aB, P.y, Q.y);
        }
        mm_tile(A, sU1b0, C, lane);
        lrelu16(C);
        c2a(C, A);
        float H[4][4];
#pragma unroll
        for (int nb = 0; nb < 4; nb++) {
            int u0 = 8 * nb + 2 * q;
            float2 B2 = *(const float2*)&sUB20[u0];
            H[nb][0] = B2.x; H[nb][1] = B2.y; H[nb][2] = B2.x; H[nb][3] = B2.y;
        }
        mm_tile(A, sU20, H, lane);       // H = h1

        // ---- layer-1 update: C = UB1 + h1 @ U1[h] + s1 @ U1[s] ----
        c2a(H, A);
#pragma unroll
        for (int nb = 0; nb < 4; nb++) {
            int u0 = 8 * nb + 2 * q;
            float2 B2 = *(const float2*)&sUB1[u0];
            C[nb][0] = B2.x; C[nb][1] = B2.y; C[nb][2] = B2.x; C[nb][3] = B2.y;
        }
        mm_tile(A, sU1, C, lane);
        gather_a(g_s1 + (size_t)nA * 32, g_s1 + (size_t)nB * 32, A, q);
        mm_tile(A, sU1 + 16 * 32, C, lane);
        lrelu16(C);

        c2a(C, A);
#pragma unroll
        for (int nb = 0; nb < 4; nb++) {
            int u0 = 8 * nb + 2 * q;
            float2 B2 = *(const float2*)&sUB2[u0];
            H[nb][0] = B2.x; H[nb][1] = B2.y; H[nb][2] = B2.x; H[nb][3] = B2.y;
        }
        mm_tile(A, sU2, H, lane);        // H = h2

        // ---- head: v1 = lrelu(a*PH + QH + h2 @ H1b) ----
        c2a(H, A);
#pragma unroll
        for (int nb = 0; nb < 4; nb++) {
            int u0 = 8 * nb + 2 * q;
            float2 P = *(const float2*)&sPH[u0];
            float2 Q = *(const float2*)&sQH[u0];
            C[nb][0] = fmaf(aA, P.x, Q.x); C[nb][1] = fmaf(aA, P.y, Q.y);
            C[nb][2] = fmaf(aB, P.x, Q.x); C[nb][3] = fmaf(aB, P.y, Q.y);
        }
        mm_tile(A, sH1b, C, lane);
        lrelu16(C);
        c2a(C, A);
#pragma unroll
        for (int nb = 0; nb < 4; nb++) {
            int u0 = 8 * nb + 2 * q;
            float2 B2 = *(const float2*)&sHB2[u0];
            C[nb][0] = B2.x; C[nb][1] = B2.y; C[nb][2] = B2.x; C[nb][3] = B2.y;
        }
        mm_tile(A, sH2, C, lane);
        lrelu16(C);

        // head dot + row reduce
        float dA = 0.f, dB = 0.f;
#pragma unroll
        for (int nb = 0; nb < 4; nb++) {
            int u0 = 8 * nb + 2 * q;
            float2 h3 = *(const float2*)&sH3[u0];
            dA = fmaf(C[nb][0], h3.x, dA); dA = fmaf(C[nb][1], h3.y, dA);
            dB = fmaf(C[nb][2], h3.x, dB); dB = fmaf(C[nb][3], h3.y, dB);
        }
        dA += __shfl_xor_sync(0xffffffffu, dA, 1);
        dA += __shfl_xor_sync(0xffffffffu, dA, 2);
        dB += __shfl_xor_sync(0xffffffffu, dB, 1);
        dB += __shfl_xor_sync(0xffffffffu, dB, 2);

        if (q == 0) {
            // unshifted softmax (logits bounded, fp32-safe)
            float exA = __expf(dA + sHB3), exB = __expf(dB + sHB3);
            out[eA] = exA;
            out[eB] = exB;
            red_add1(&g_dsum[nA], exA);
            red_add1(&g_dsum[nB], exB);
        }
    }
}

// ---------------- K4: normalize ----------------
__global__ void k4(const int* __restrict__ idx, float* __restrict__ out) {
    int e = blockIdx.x * blockDim.x + threadIdx.x;
    if (e >= E_EDGES) return;
    out[e] = out[e] / g_dsum[idx[e]];
}

// ---------------- launcher ----------------
extern "C" void kernel_launch(void* const* d_in, const int* in_sizes, int n_in,
                              void* d_out, int out_size) {
    const float* ea   = (const float*)d_in[0];
    const int*   eidx = (const int*)d_in[1];
    const float* w_in = (const float*)d_in[2];
    const float* b_in = (const float*)d_in[3];
    const float* tw1  = (const float*)d_in[4];
    const float* tb1  = (const float*)d_in[5];
    const float* tw2  = (const float*)d_in[6];
    const float* tb2  = (const float*)d_in[7];
    const float* uw1  = (const float*)d_in[8];
    const float* ub1  = (const float*)d_in[9];
    const float* uw2  = (const float*)d_in[10];
    const float* ub2  = (const float*)d_in[11];
    const float* hw1  = (const float*)d_in[12];
    const float* hb1  = (const float*)d_in[13];
    const float* hw2  = (const float*)d_in[14];
    const float* hb2  = (const float*)d_in[15];
    const float* hw3  = (const float*)d_in[16];
    const float* hb3  = (const float*)d_in[17];
    float* out = (float*)d_out;

    const int TB = 256;
    kinit<<<(N_NODES * D + TB - 1) / TB, TB>>>();
    const int GB = 2048;   // grid-stride over warp-tiles (8 tiles / block / iter)
    k0<<<GB, 256>>>(ea, eidx, w_in, b_in, tw1, tb1, tw2, tb2);
    k1<<<GB, 256>>>(ea, eidx, w_in, b_in, tw1, tb1, tw2, tb2, uw1, ub1, uw2, ub2);
    k2<<<GB, 256>>>(ea, eidx, w_in, b_in, uw1, ub1, uw2, ub2,
                    hw1, hb1, hw2, hb2, hw3, hb3, out);
    int gb = (E_EDGES + TB - 1) / TB;
    k4<<<gb, TB>>>(eidx, out);
}

// round 6
// speedup vs baseline: 5.0092x; 1.2138x over previous
#include <cuda_runtime.h>

#define E_EDGES 2000000
#define N_NODES 50000
#define D 32
#define NTILES (E_EDGES / 16)

// ---------------- scratch ----------------
__device__ float g_s0[N_NODES * D];            // segment sums layer 0 (natural order)
__device__ float g_s1[N_NODES * D];            // segment sums layer 1 (natural order)
__device__ float g_dsum[N_NODES];              // softmax denominators

__device__ __forceinline__ float lrelu(float x) { return fmaxf(x, 0.01f * x); }
__device__ __forceinline__ void red_add2(float* p, float a, float b) {
    asm volatile("red.global.add.v2.f32 [%0], {%1,%2};" :: "l"(p), "f"(a), "f"(b) : "memory");
}
__device__ __forceinline__ void red_add1(float* p, float v) {
    asm volatile("red.global.add.f32 [%0], %1;" :: "l"(p), "f"(v) : "memory");
}

// pack two f32 -> f16x2 (lo = first element)
__device__ __forceinline__ unsigned packh2(float lo, float hi) {
    unsigned r; asm("cvt.rn.f16x2.f32 %0, %1, %2;" : "=r"(r) : "f"(hi), "f"(lo)); return r;
}

// m16n8k16 fp16 MMA, fp32 accum
__device__ __forceinline__ void mma16(float& c0, float& c1, float& c2, float& c3,
                                      unsigned a0, unsigned a1, unsigned a2, unsigned a3,
                                      unsigned b0, unsigned b1) {
    asm("mma.sync.aligned.m16n8k16.row.col.f32.f16.f16.f32 "
        "{%0,%1,%2,%3},{%4,%5,%6,%7},{%8,%9},{%0,%1,%2,%3};"
        : "+f"(c0), "+f"(c1), "+f"(c2), "+f"(c3)
        : "r"(a0), "r"(a1), "r"(a2), "r"(a3), "r"(b0), "r"(b1));
}

// C[16,32] += A[16,32] @ W   (2 kblocks x 4 nblocks, fp16)
__device__ __forceinline__ void mm_tile(const unsigned A[2][4], const uint2* sB,
                                        float C[4][4], int lane) {
#pragma unroll
    for (int kb = 0; kb < 2; kb++)
#pragma unroll
        for (int nb = 0; nb < 4; nb++) {
            uint2 b = sB[(kb * 4 + nb) * 32 + lane];
            mma16(C[nb][0], C[nb][1], C[nb][2], C[nb][3],
                  A[kb][0], A[kb][1], A[kb][2], A[kb][3], b.x, b.y);
        }
}

// chain: C-frag (natural layout) -> A-frag of next matmul (pure adjacent-pair packing)
__device__ __forceinline__ void c2a(const float C[4][4], unsigned A[2][4]) {
#pragma unroll
    for (int kb = 0; kb < 2; kb++) {
        A[kb][0] = packh2(C[2 * kb][0],     C[2 * kb][1]);
        A[kb][1] = packh2(C[2 * kb][2],     C[2 * kb][3]);
        A[kb][2] = packh2(C[2 * kb + 1][0], C[2 * kb + 1][1]);
        A[kb][3] = packh2(C[2 * kb + 1][2], C[2 * kb + 1][3]);
    }
}

__device__ __forceinline__ void lrelu16(float C[4][4]) {
#pragma unroll
    for (int b = 0; b < 4; b++)
#pragma unroll
        for (int r = 0; r < 4; r++) C[b][r] = lrelu(C[b][r]);
}

// load natural-order 32-vectors (rows g / g+8 of the tile) into fp16 A-frags
__device__ __forceinline__ void gather_a(const float* __restrict__ base0,
                                         const float* __restrict__ base1,
                                         unsigned A[2][4], int t) {
#pragma unroll
    for (int kb = 0; kb < 2; kb++) {
        float2 v0 = *(const float2*)(base0 + 16 * kb + 2 * t);
        float2 v1 = *(const float2*)(base1 + 16 * kb + 2 * t);
        float2 v2 = *(const float2*)(base0 + 16 * kb + 2 * t + 8);
        float2 v3 = *(const float2*)(base1 + 16 * kb + 2 * t + 8);
        A[kb][0] = packh2(v0.x, v0.y);
        A[kb][1] = packh2(v1.x, v1.y);
        A[kb][2] = packh2(v2.x, v2.y);
        A[kb][3] = packh2(v3.x, v3.y);
    }
}

// fill fp16 B-fragments: dst[(kb*4+nb)*32+lane] =
//   { pack(W[16kb+2t][8nb+g], W[16kb+2t+1][8nb+g]), pack(W[16kb+2t+8][...], W[16kb+2t+9][...]) }
__device__ void fill_bfrag(uint2* dst, const float* __restrict__ W, int kblocks) {
    for (int i = threadIdx.x; i < kblocks * 4 * 32; i += blockDim.x) {
        int lane = i & 31, pi = i >> 5;
        int kb = pi >> 2, nb = pi & 3;
        int t = lane & 3, g = lane >> 2;
        int col = 8 * nb + g;
        int k0r = 16 * kb + 2 * t;
        uint2 v;
        v.x = packh2(W[k0r * 32 + col],       W[(k0r + 1) * 32 + col]);
        v.y = packh2(W[(k0r + 8) * 32 + col], W[(k0r + 9) * 32 + col]);
        dst[pi * 32 + lane] = v;
    }
}

// ---------------- init ----------------
__global__ void kinit() {
    int i = blockIdx.x * blockDim.x + threadIdx.x;
    if (i < N_NODES * D) { g_s0[i] = 0.f; g_s1[i] = 0.f; }
    if (i < N_NODES)     { g_dsum[i] = 0.f; }
}

// ---------------- K0: t0 = TMLP0(h0) (rank-1 folded) -> scatter s0 ----------------
__global__ __launch_bounds__(256, 2)
void k0(const float* __restrict__ ea, const int* __restrict__ idx,
        const float* __restrict__ w_in, const float* __restrict__ b_in,
        const float* __restrict__ tw1, const float* __restrict__ tb1,
        const float* __restrict__ tw2, const float* __restrict__ tb2) {
    __shared__ uint2 sT2[256];
    __shared__ __align__(8) float sPT[32], sQT[32], sTB2[32];
    int t0_ = threadIdx.x;
    if (t0_ < 32) {
        float p = 0.f, qv = 0.f;
        for (int k = 0; k < 32; ++k) {
            p  = fmaf(w_in[k], tw1[k * 32 + t0_], p);
            qv = fmaf(b_in[k], tw1[k * 32 + t0_], qv);
        }
        sPT[t0_] = p; sQT[t0_] = qv + tb1[t0_];
        sTB2[t0_] = tb2[t0_];
    }
    fill_bfrag(sT2, tw2, 2);
    __syncthreads();

    int lane = t0_ & 31, warp = t0_ >> 5;
    int t = lane & 3, g = lane >> 2;
    for (int tile = blockIdx.x * 8 + warp; tile < NTILES; tile += gridDim.x * 8) {
        int e0 = tile * 16;
        int eA = e0 + g, eB = eA + 8;
        float aA = ea[eA], aB = ea[eB];
        int nA = idx[eA], nB = idx[eB];

        unsigned A[2][4];
#pragma unroll
        for (int kb = 0; kb < 2; kb++) {
            int c0 = 16 * kb + 2 * t;
            float2 P0 = *(const float2*)&sPT[c0],     Q0 = *(const float2*)&sQT[c0];
            float2 P1 = *(const float2*)&sPT[c0 + 8], Q1 = *(const float2*)&sQT[c0 + 8];
            A[kb][0] = packh2(lrelu(fmaf(aA, P0.x, Q0.x)), lrelu(fmaf(aA, P0.y, Q0.y)));
            A[kb][1] = packh2(lrelu(fmaf(aB, P0.x, Q0.x)), lrelu(fmaf(aB, P0.y, Q0.y)));
            A[kb][2] = packh2(lrelu(fmaf(aA, P1.x, Q1.x)), lrelu(fmaf(aA, P1.y, Q1.y)));
            A[kb][3] = packh2(lrelu(fmaf(aB, P1.x, Q1.x)), lrelu(fmaf(aB, P1.y, Q1.y)));
        }
        float C[4][4];
#pragma unroll
        for (int nb = 0; nb < 4; nb++) {
            float2 B2 = *(const float2*)&sTB2[8 * nb + 2 * t];
            C[nb][0] = B2.x; C[nb][1] = B2.y; C[nb][2] = B2.x; C[nb][3] = B2.y;
        }
        mm_tile(A, sT2, C, lane);

        float* pA = g_s0 + (size_t)nA * 32;
        float* pB = g_s0 + (size_t)nB * 32;
#pragma unroll
        for (int nb = 0; nb < 4; nb++) {
            int u0 = 8 * nb + 2 * t;
            red_add2(pA + u0, C[nb][0], C[nb][1]);
            red_add2(pB + u0, C[nb][2], C[nb][3]);
        }
    }
}

// ---------------- K1: h1 = UPD0(h0,s0[idx]); t1 = TMLP1(h1) -> scatter s1 ---------
__global__ __launch_bounds__(256, 2)
void k1(const float* __restrict__ ea, const int* __restrict__ idx,
        const float* __restrict__ w_in, const float* __restrict__ b_in,
        const float* __restrict__ tw1, const float* __restrict__ tb1,
        const float* __restrict__ tw2, const float* __restrict__ tb2,
        const float* __restrict__ uw1, const float* __restrict__ ub1,
        const float* __restrict__ uw2, const float* __restrict__ ub2) {
    __shared__ uint2 sU1b[256], sU2[256], sT1[256], sT2[256];
    __shared__ __align__(8) float sPU[32], sQU[32], sUB2[32], sTB1[32], sTB2[32];
    int tid = threadIdx.x;
    if (tid < 32) {
        float p = 0.f, qv = 0.f;
        for (int k = 0; k < 32; ++k) {
            p  = fmaf(w_in[k], uw1[k * 32 + tid], p);
            qv = fmaf(b_in[k], uw1[k * 32 + tid], qv);
        }
        sPU[tid] = p; sQU[tid] = qv + ub1[tid];
        sUB2[tid] = ub2[tid];
        sTB1[tid] = tb1[32 + tid];
        sTB2[tid] = tb2[32 + tid];
    }
    fill_bfrag(sU1b, uw1 + 1024, 2);   // uw1[0] rows 32..63
    fill_bfrag(sU2,  uw2, 2);          // uw2[0]
    fill_bfrag(sT1,  tw1 + 1024, 2);   // tw1[1]
    fill_bfrag(sT2,  tw2 + 1024, 2);   // tw2[1]
    __syncthreads();

    int lane = tid & 31, warp = tid >> 5;
    int t = lane & 3, g = lane >> 2;
    for (int tile = blockIdx.x * 8 + warp; tile < NTILES; tile += gridDim.x * 8) {
        int e0 = tile * 16;
        int eA = e0 + g, eB = eA + 8;
        float aA = ea[eA], aB = ea[eB];
        int nA = idx[eA], nB = idx[eB];

        unsigned A[2][4];
        gather_a(g_s0 + (size_t)nA * 32, g_s0 + (size_t)nB * 32, A, t);

        float C[4][4];
#pragma unroll
        for (int nb = 0; nb < 4; nb++) {
            int u0 = 8 * nb + 2 * t;
            float2 P = *(const float2*)&sPU[u0];
            float2 Q = *(const float2*)&sQU[u0];
            C[nb][0] = fmaf(aA, P.x, Q.x); C[nb][1] = fmaf(aA, P.y, Q.y);
            C[nb][2] = fmaf(aB, P.x, Q.x); C[nb][3] = fmaf(aB, P.y, Q.y);
        }
        mm_tile(A, sU1b, C, lane);
        lrelu16(C);
        c2a(C, A);

        float H[4][4];
#pragma unroll
        for (int nb = 0; nb < 4; nb++) {
            float2 B2 = *(const float2*)&sUB2[8 * nb + 2 * t];
            H[nb][0] = B2.x; H[nb][1] = B2.y; H[nb][2] = B2.x; H[nb][3] = B2.y;
        }
        mm_tile(A, sU2, H, lane);       // H = h1

        // T layer 1
        c2a(H, A);
#pragma unroll
        for (int nb = 0; nb < 4; nb++) {
            float2 B2 = *(const float2*)&sTB1[8 * nb + 2 * t];
            C[nb][0] = B2.x; C[nb][1] = B2.y; C[nb][2] = B2.x; C[nb][3] = B2.y;
        }
        mm_tile(A, sT1, C, lane);
        lrelu16(C);
        c2a(C, A);
#pragma unroll
        for (int nb = 0; nb < 4; nb++) {
            float2 B2 = *(const float2*)&sTB2[8 * nb + 2 * t];
            C[nb][0] = B2.x; C[nb][1] = B2.y; C[nb][2] = B2.x; C[nb][3] = B2.y;
        }
        mm_tile(A, sT2, C, lane);

        float* pA = g_s1 + (size_t)nA * 32;
        float* pB = g_s1 + (size_t)nB * 32;
#pragma unroll
        for (int nb = 0; nb < 4; nb++) {
            int u0 = 8 * nb + 2 * t;
            red_add2(pA + u0, C[nb][0], C[nb][1]);
            red_add2(pB + u0, C[nb][2], C[nb][3]);
        }
    }
}

// ---- K2: recompute h1 from s0 (L2-resident); h2 = UPD1; head; exp; red denom -----
__global__ __launch_bounds__(256, 2)
void k2(const float* __restrict__ ea, const int* __restrict__ idx,
        const float* __restrict__ w_in, const float* __restrict__ b_in,
        const float* __restrict__ uw1, const float* __restrict__ ub1,
        const float* __restrict__ uw2, const float* __restrict__ ub2,
        const float* __restrict__ hw1, const float* __restrict__ hb1,
        const float* __restrict__ hw2, const float* __restrict__ hb2,
        const float* __restrict__ hw3, const float* __restrict__ hb3,
        float* __restrict__ out) {
    __shared__ uint2 sU1[512];                  // uw1[1] full 64x32 (4 kblocks)
    __shared__ uint2 sU2[256], sH1b[256], sH2[256];
    __shared__ uint2 sU1b0[256], sU20[256];     // layer-0 U weights for h1 recompute
    __shared__ __align__(8) float sUB1[32], sUB2[32], sPH[32], sQH[32], sHB2[32], sH3[32];
    __shared__ __align__(8) float sPU[32], sQU[32], sUB20[32];
    __shared__ float sHB3;
    int tid = threadIdx.x;
    const float* u1 = uw1 + 2048;               // uw1[1]
    if (tid < 32) {
        float p = 0.f, qv = 0.f, pu = 0.f, qu = 0.f;
        for (int k = 0; k < 32; ++k) {
            p  = fmaf(w_in[k], hw1[k * 32 + tid], p);
            qv = fmaf(b_in[k], hw1[k * 32 + tid], qv);
            pu = fmaf(w_in[k], uw1[k * 32 + tid], pu);
            qu = fmaf(b_in[k], uw1[k * 32 + tid], qu);
        }
        sPH[tid] = p;  sQH[tid] = qv + hb1[tid];
        sPU[tid] = pu; sQU[tid] = qu + ub1[tid];
        sUB20[tid] = ub2[tid];
        sUB1[tid] = ub1[32 + tid];
        sUB2[tid] = ub2[32 + tid];
        sHB2[tid] = hb2[tid];
        sH3[tid]  = hw3[tid];
    }
    if (tid == 0) sHB3 = hb3[0];
    fill_bfrag(sU1,   u1, 4);           // 64 rows: kb0..1 = h-part, kb2..3 = s-part
    fill_bfrag(sU2,   uw2 + 1024, 2);   // uw2[1]
    fill_bfrag(sH1b,  hw1 + 1024, 2);   // hw1 rows 32..63
    fill_bfrag(sH2,   hw2, 2);
    fill_bfrag(sU1b0, uw1 + 1024, 2);   // uw1[0] rows 32..63
    fill_bfrag(sU20,  uw2, 2);          // uw2[0]
    __syncthreads();

    int lane = tid & 31, warp = tid >> 5;
    int t = lane & 3, g = lane >> 2;
    for (int tile = blockIdx.x * 8 + warp; tile < NTILES; tile += gridDim.x * 8) {
        int e0 = tile * 16;
        int eA = e0 + g, eB = eA + 8;
        float aA = ea[eA], aB = ea[eB];
        int nA = idx[eA], nB = idx[eB];

        // ---- recompute h1 (layer-0 update) from s0 gather (L2) ----
        unsigned A[2][4];
        gather_a(g_s0 + (size_t)nA * 32, g_s0 + (size_t)nB * 32, A, t);
        float C[4][4];
#pragma unroll
        for (int nb = 0; nb < 4; nb++) {
            int u0 = 8 * nb + 2 * t;
            float2 P = *(const float2*)&sPU[u0];
            float2 Q = *(const float2*)&sQU[u0];
            C[nb][0] = fmaf(aA, P.x, Q.x); C[nb][1] = fmaf(aA, P.y, Q.y);
            C[nb][2] = fmaf(aB, P.x, Q.x); C[nb][3] = fmaf(aB, P.y, Q.y);
        }
        mm_tile(A, sU1b0, C, lane);
        lrelu16(C);
        c2a(C, A);
        float H[4][4];
#pragma unroll
        for (int nb = 0; nb < 4; nb++) {
            float2 B2 = *(const float2*)&sUB20[8 * nb + 2 * t];
            H[nb][0] = B2.x; H[nb][1] = B2.y; H[nb][2] = B2.x; H[nb][3] = B2.y;
        }
        mm_tile(A, sU20, H, lane);       // H = h1

        // ---- layer-1 update: C = UB1 + h1 @ U1[h] + s1 @ U1[s] ----
        c2a(H, A);
#pragma unroll
        for (int nb = 0; nb < 4; nb++) {
            float2 B2 = *(const float2*)&sUB1[8 * nb + 2 * t];
            C[nb][0] = B2.x; C[nb][1] = B2.y; C[nb][2] = B2.x; C[nb][3] = B2.y;
        }
        mm_tile(A, sU1, C, lane);
        gather_a(g_s1 + (size_t)nA * 32, g_s1 + (size_t)nB * 32, A, t);
        mm_tile(A, sU1 + 8 * 32, C, lane);
        lrelu16(C);

        c2a(C, A);
#pragma unroll
        for (int nb = 0; nb < 4; nb++) {
            float2 B2 = *(const float2*)&sUB2[8 * nb + 2 * t];
            H[nb][0] = B2.x; H[nb][1] = B2.y; H[nb][2] = B2.x; H[nb][3] = B2.y;
        }
        mm_tile(A, sU2, H, lane);        // H = h2

        // ---- head: v1 = lrelu(a*PH + QH + h2 @ H1b) ----
        c2a(H, A);
#pragma unroll
        for (int nb = 0; nb < 4; nb++) {
            int u0 = 8 * nb + 2 * t;
            float2 P = *(const float2*)&sPH[u0];
            float2 Q = *(const float2*)&sQH[u0];
            C[nb][0] = fmaf(aA, P.x, Q.x); C[nb][1] = fmaf(aA, P.y, Q.y);
            C[nb][2] = fmaf(aB, P.x, Q.x); C[nb][3] = fmaf(aB, P.y, Q.y);
        }
        mm_tile(A, sH1b, C, lane);
        lrelu16(C);
        c2a(C, A);
#pragma unroll
        for (int nb = 0; nb < 4; nb++) {
            float2 B2 = *(const float2*)&sHB2[8 * nb + 2 * t];
            C[nb][0] = B2.x; C[nb][1] = B2.y; C[nb][2] = B2.x; C[nb][3] = B2.y;
        }
        mm_tile(A, sH2, C, lane);
        lrelu16(C);

        // head dot + row reduce
        float dA = 0.f, dB = 0.f;
#pragma unroll
        for (int nb = 0; nb < 4; nb++) {
            float2 h3 = *(const float2*)&sH3[8 * nb + 2 * t];
            dA = fmaf(C[nb][0], h3.x, dA); dA = fmaf(C[nb][1], h3.y, dA);
            dB = fmaf(C[nb][2], h3.x, dB); dB = fmaf(C[nb][3], h3.y, dB);
        }
        dA += __shfl_xor_sync(0xffffffffu, dA, 1);
        dA += __shfl_xor_sync(0xffffffffu, dA, 2);
        dB += __shfl_xor_sync(0xffffffffu, dB, 1);
        dB += __shfl_xor_sync(0xffffffffu, dB, 2);

        if (t == 0) {
            // unshifted softmax (logits bounded, fp32-safe)
            float exA = __expf(dA + sHB3), exB = __expf(dB + sHB3);
            out[eA] = exA;
            out[eB] = exB;
            red_add1(&g_dsum[nA], exA);
            red_add1(&g_dsum[nB], exB);
        }
    }
}

// ---------------- K4: normalize ----------------
__global__ void k4(const int* __restrict__ idx, float* __restrict__ out) {
    int e = blockIdx.x * blockDim.x + threadIdx.x;
    if (e >= E_EDGES) return;
    out[e] = out[e] / g_dsum[idx[e]];
}

// ---------------- launcher ----------------
extern "C" void kernel_launch(void* const* d_in, const int* in_sizes, int n_in,
                              void* d_out, int out_size) {
    const float* ea   = (const float*)d_in[0];
    const int*   eidx = (const int*)d_in[1];
    const float* w_in = (const float*)d_in[2];
    const float* b_in = (const float*)d_in[3];
    const float* tw1  = (const float*)d_in[4];
    const float* tb1  = (const float*)d_in[5];
    const float* tw2  = (const float*)d_in[6];
    const float* tb2  = (const float*)d_in[7];
    const float* uw1  = (const float*)d_in[8];
    const float* ub1  = (const float*)d_in[9];
    const float* uw2  = (const float*)d_in[10];
    const float* ub2  = (const float*)d_in[11];
    const float* hw1  = (const float*)d_in[12];
    const float* hb1  = (const float*)d_in[13];
    const float* hw2  = (const float*)d_in[14];
    const float* hb2  = (const float*)d_in[15];
    const float* hw3  = (const float*)d_in[16];
    const float* hb3  = (const float*)d_in[17];
    float* out = (float*)d_out;

    const int TB = 256;
    kinit<<<(N_NODES * D + TB - 1) / TB, TB>>>();
    const int GB = 2048;   // grid-stride over warp-tiles (8 tiles / block / iter)
    k0<<<GB, 256>>>(ea, eidx, w_in, b_in, tw1, tb1, tw2, tb2);
    k1<<<GB, 256>>>(ea, eidx, w_in, b_in, tw1, tb1, tw2, tb2, uw1, ub1, uw2, ub2);
    k2<<<GB, 256>>>(ea, eidx, w_in, b_in, uw1, ub1, uw2, ub2,
                    hw1, hb1, hw2, hb2, hw3, hb3, out);
    int gb = (E_EDGES + TB - 1) / TB;
    k4<<<gb, TB>>>(eidx, out);
}